// round 11
// baseline (speedup 1.0000x reference)
#include <cuda_runtime.h>
#include <cstdint>
#include <math.h>

// Problem constants
#define BN    2
#define LEN   2048
#define HALFD 1024
#define NH    16
#define HD    64
#define MROWS (BN * LEN)        // 4096
#define ELEMS (MROWS * HALFD)   // 4194304 per tensor

// Scratch (device globals: no allocation allowed)
__device__ float g_qa[ELEMS];
__device__ float g_ka[ELEMS];
__device__ float g_va[ELEMS];
__device__ float g_qb[ELEMS];
__device__ float g_kb[ELEMS];
__device__ float g_vb[ELEMS];
__device__ float g_oa[ELEMS];
__device__ float g_ob[ELEMS];
__device__ float g_pa[ELEMS];
__device__ float g_pb[ELEMS];
__device__ float g_vaT[ELEMS];   // [bh][64][2048] transposed V, branch a
__device__ float g_vbT[ELEMS];   // [bh][64][2048] transposed V, branch b

#if defined(__CUDA_ARCH__) && (defined(__CUDA_ARCH_FEAT_SM103_ALL) || \
    defined(__CUDA_ARCH_FEAT_SM100_ALL) || defined(__CUDA_ARCH_FEAT_SM101_ALL))
#define HAS_TCGEN05 1
#else
#define HAS_TCGEN05 0
#endif

// ---------------------------------------------------------------------------
// packed f32x2 helpers (legal in plain pass)
// ---------------------------------------------------------------------------
__device__ __forceinline__ uint64_t pk2(float lo, float hi) {
    uint64_t r;
    asm("mov.b64 %0, {%1, %2};" : "=l"(r) : "f"(lo), "f"(hi));
    return r;
}
__device__ __forceinline__ void upk2(uint64_t v, float& lo, float& hi) {
    asm("mov.b64 {%0, %1}, %2;" : "=f"(lo), "=f"(hi) : "l"(v));
}
__device__ __forceinline__ uint64_t fma2(uint64_t a, uint64_t b, uint64_t c) {
    uint64_t d;
    asm("fma.rn.f32x2 %0, %1, %2, %3;" : "=l"(d) : "l"(a), "l"(b), "l"(c));
    return d;
}
__device__ __forceinline__ uint64_t mul2(uint64_t a, uint64_t b) {
    uint64_t d;
    asm("mul.rn.f32x2 %0, %1, %2;" : "=l"(d) : "l"(a), "l"(b));
    return d;
}

// ---------------------------------------------------------------------------
// common asm helpers
// ---------------------------------------------------------------------------
#define SWZ(off) ((off) ^ (((off) >> 3) & 0x70))

__device__ __forceinline__ uint32_t smem_u32(const void* p) {
    uint32_t a;
    asm("{ .reg .u64 t; cvta.to.shared.u64 t, %1; cvt.u32.u64 %0, t; }"
        : "=r"(a) : "l"(p));
    return a;
}
__device__ __forceinline__ void cp16(uint32_t dst, const void* src) {
    asm volatile("cp.async.cg.shared.global [%0], [%1], 16;" :: "r"(dst), "l"(src));
}
__device__ __forceinline__ void cp_commit() {
    asm volatile("cp.async.commit_group;" ::: "memory");
}
__device__ __forceinline__ void cp_wait2() {
    asm volatile("cp.async.wait_group 2;" ::: "memory");
}
__device__ __forceinline__ void cp_wait1() {
    asm volatile("cp.async.wait_group 1;" ::: "memory");
}
__device__ __forceinline__ void cp_wait0() {
    asm volatile("cp.async.wait_group 0;" ::: "memory");
}

#if HAS_TCGEN05
__device__ __forceinline__ uint32_t elect1() {
    uint32_t p;
    asm volatile("{ .reg .pred p; elect.sync _|p, 0xFFFFFFFF; selp.b32 %0,1,0,p; }"
                 : "=r"(p));
    return p;
}
__device__ __forceinline__ void mbar_init(uint32_t a, uint32_t cnt) {
    asm volatile("mbarrier.init.shared.b64 [%0], %1;" :: "r"(a), "r"(cnt) : "memory");
}
__device__ __forceinline__ void mbar_wait(uint32_t a, uint32_t par) {
    asm volatile(
        "{\n\t.reg .pred P;\n"
        "W_%=:\n\t"
        "mbarrier.try_wait.parity.acquire.cta.shared::cta.b64 P, [%0], %1, 0x989680;\n\t"
        "@!P bra W_%=;\n\t}"
        :: "r"(a), "r"(par) : "memory");
}
// cluster-scope acquire wait (for cross-CTA handshakes in cg2 GEMM)
__device__ __forceinline__ void mbar_waitc(uint32_t a, uint32_t par) {
    asm volatile(
        "{\n\t.reg .pred P;\n"
        "W_%=:\n\t"
        "mbarrier.try_wait.parity.acquire.cluster.shared::cta.b64 P, [%0], %1, 0x989680;\n\t"
        "@!P bra W_%=;\n\t}"
        :: "r"(a), "r"(par) : "memory");
}
// arrive on rank0's barrier at the same smem offset (release, cluster scope)
__device__ __forceinline__ void mbar_arrive_rank0(uint32_t local_addr) {
    asm volatile(
        "{\n\t.reg .b32 ra;\n\t"
        "mapa.shared::cluster.u32 ra, %0, 0;\n\t"
        "mbarrier.arrive.release.cluster.shared::cluster.b64 _, [ra];\n\t}"
        :: "r"(local_addr) : "memory");
}
__device__ __forceinline__ void tc_commit(uint32_t mbar) {
    asm volatile(
        "tcgen05.commit.cta_group::1.mbarrier::arrive::one.shared::cluster.b64 [%0];"
        :: "r"(mbar) : "memory");
}
__device__ __forceinline__ void tc_commit_mc2(uint32_t mbar) {
    asm volatile(
        "tcgen05.commit.cta_group::2.mbarrier::arrive::one.shared::cluster.multicast::cluster.b64 [%0], %1;"
        :: "r"(mbar), "h"((uint16_t)0x3) : "memory");
}
__device__ __forceinline__ uint64_t mk_desc(uint32_t addr) {
    const uint64_t base = (uint64_t(2) << 61) | (uint64_t(1) << 46)
                        | (uint64_t(64) << 32) | (uint64_t(1) << 16);
    return base | ((uint64_t)(addr >> 4) & 0x3FFF);
}
__device__ __forceinline__ void mma_tf32_ss(uint32_t d, uint64_t ad, uint64_t bd,
                                            uint32_t idesc, uint32_t en) {
    asm volatile(
        "{\n\t.reg .pred p;\n\t"
        "setp.ne.u32 p, %4, 0;\n\t"
        "tcgen05.mma.cta_group::1.kind::tf32 [%0], %1, %2, %3, {%5,%5,%5,%5}, p;\n\t}"
        :: "r"(d), "l"(ad), "l"(bd), "r"(idesc), "r"(en), "r"(0u)
        : "memory");
}
__device__ __forceinline__ void mma_tf32_ss_cg2(uint32_t d, uint64_t ad, uint64_t bd,
                                                uint32_t idesc, uint32_t en) {
    asm volatile(
        "{\n\t.reg .pred p;\n\t"
        "setp.ne.u32 p, %4, 0;\n\t"
        "tcgen05.mma.cta_group::2.kind::tf32 [%0], %1, %2, %3, "
        "{%5,%5,%5,%5,%5,%5,%5,%5}, p;\n\t}"
        :: "r"(d), "l"(ad), "l"(bd), "r"(idesc), "r"(en), "r"(0u)
        : "memory");
}
__device__ __forceinline__ void mma_tf32_ts(uint32_t d, uint32_t a, uint64_t bd,
                                            uint32_t idesc, uint32_t en) {
    asm volatile(
        "{\n\t.reg .pred p;\n\t"
        "setp.ne.u32 p, %4, 0;\n\t"
        "tcgen05.mma.cta_group::1.kind::tf32 [%0], [%1], %2, %3, {%5,%5,%5,%5}, p;\n\t}"
        :: "r"(d), "r"(a), "l"(bd), "r"(idesc), "r"(en), "r"(0u)
        : "memory");
}
#define CLUSTER_SYNC_() do { \
    asm volatile("barrier.cluster.arrive.aligned;" ::: "memory"); \
    asm volatile("barrier.cluster.wait.aligned;" ::: "memory"); } while (0)

#define LDTM_X32(r, addr) \
    asm volatile( \
        "tcgen05.ld.sync.aligned.32x32b.x32.b32 " \
        "{%0,%1,%2,%3,%4,%5,%6,%7,%8,%9,%10,%11,%12,%13,%14,%15," \
        "%16,%17,%18,%19,%20,%21,%22,%23,%24,%25,%26,%27,%28,%29,%30,%31}, [%32];" \
        : "=r"((r)[0]), "=r"((r)[1]), "=r"((r)[2]), "=r"((r)[3]), \
          "=r"((r)[4]), "=r"((r)[5]), "=r"((r)[6]), "=r"((r)[7]), \
          "=r"((r)[8]), "=r"((r)[9]), "=r"((r)[10]), "=r"((r)[11]), \
          "=r"((r)[12]), "=r"((r)[13]), "=r"((r)[14]), "=r"((r)[15]), \
          "=r"((r)[16]), "=r"((r)[17]), "=r"((r)[18]), "=r"((r)[19]), \
          "=r"((r)[20]), "=r"((r)[21]), "=r"((r)[22]), "=r"((r)[23]), \
          "=r"((r)[24]), "=r"((r)[25]), "=r"((r)[26]), "=r"((r)[27]), \
          "=r"((r)[28]), "=r"((r)[29]), "=r"((r)[30]), "=r"((r)[31]) \
        : "r"(addr))

#define STTM_X32(addr, r) \
    asm volatile( \
        "tcgen05.st.sync.aligned.32x32b.x32.b32 [%0], " \
        "{%1,%2,%3,%4,%5,%6,%7,%8,%9,%10,%11,%12,%13,%14,%15,%16," \
        "%17,%18,%19,%20,%21,%22,%23,%24,%25,%26,%27,%28,%29,%30,%31,%32};" \
        :: "r"(addr), \
           "r"((r)[0]), "r"((r)[1]), "r"((r)[2]), "r"((r)[3]), \
           "r"((r)[4]), "r"((r)[5]), "r"((r)[6]), "r"((r)[7]), \
           "r"((r)[8]), "r"((r)[9]), "r"((r)[10]), "r"((r)[11]), \
           "r"((r)[12]), "r"((r)[13]), "r"((r)[14]), "r"((r)[15]), \
           "r"((r)[16]), "r"((r)[17]), "r"((r)[18]), "r"((r)[19]), \
           "r"((r)[20]), "r"((r)[21]), "r"((r)[22]), "r"((r)[23]), \
           "r"((r)[24]), "r"((r)[25]), "r"((r)[26]), "r"((r)[27]), \
           "r"((r)[28]), "r"((r)[29]), "r"((r)[30]), "r"((r)[31]) \
        : "memory")
#endif  // HAS_TCGEN05

// ---------------------------------------------------------------------------
// Projection GEMM, cta_group::2: cluster (2,1,1) computes one 256x256 tile.
// Each CTA holds its 128 A-rows + 128 B-rows per K stage (32 floats = 128B
// rows, SW128). Rank 0 issues 4 cg2 MMAs/stage (M=256, halved dispatch
// cycles); commit is multicast to both CTAs' per-buffer mbars. Per-stage
// readiness: each CTA arrives on rank0's LM[buf] (count 2).
// ---------------------------------------------------------------------------
#define GTM 256
#define GTN 256
#define KSTEP 32
#define NSTAGES (HALFD / KSTEP)     // 32
#define G2_ABYTES  16384            // 128 rows x 128B per CTA
#define G2_BUFSTRIDE 32768
#define SM_MBAR  8                  // LM[3] @ +0..16 (cnt 2), MM[3] @ +24..40 (cnt 1)
#define SM_TILES 1024
#define SMEM_GEMM_TOTAL (SM_TILES + 3 * G2_BUFSTRIDE)   // 99328

// idesc: M=256, N=256, tf32
#define IDESC_G2 ((1u<<4)|(2u<<7)|(2u<<10)|(32u<<17)|(16u<<24))

#if HAS_TCGEN05
// per CTA per stage: 16KB A + 16KB B; 256 threads x (4+4) cp16
__device__ __forceinline__ void g2_load_stage(uint32_t sm_base,
                                              const float* __restrict__ A,
                                              const float* __restrict__ W,
                                              int am0, int bn0, int s, int buf, int t)
{
    const int k0 = s * KSTEP;
    const uint32_t abase = sm_base + SM_TILES + buf * G2_BUFSTRIDE;
    const uint32_t bbase = abase + G2_ABYTES;
#pragma unroll
    for (int i = 0; i < 4; i++) {
        const int ch = t + i * 256;       // 0..1023
        const int r = ch >> 3;
        const int c16 = ch & 7;
        const uint32_t off = r * 128 + c16 * 16;
        cp16(abase + SWZ(off), A + (size_t)(am0 + r) * HALFD + k0 + c16 * 4);
    }
#pragma unroll
    for (int i = 0; i < 4; i++) {
        const int ch = t + i * 256;
        const int r = ch >> 3;
        const int c16 = ch & 7;
        const uint32_t off = r * 128 + c16 * 16;
        cp16(bbase + SWZ(off), W + (size_t)(bn0 + r) * HALFD + k0 + c16 * 4);
    }
}
#endif

#if !HAS_TCGEN05
// SIMT f32x2 128x128 sub-tile (fallback only)
__device__ void gemm128_fb(const float* __restrict__ A,
                           const float* __restrict__ W,
                           float* __restrict__ C, int bm, int bn)
{
    __shared__ float As[16][128];
    __shared__ float Bs[16][128];
    const int t  = threadIdx.x;
    const int tm = (t >> 4) * 8;
    const int tn = (t & 15) * 8;

    uint64_t acc2[8][4];
#pragma unroll
    for (int i = 0; i < 8; i++)
#pragma unroll
        for (int j = 0; j < 4; j++) acc2[i][j] = 0ull;

    const int lrow = t >> 2;
    const int lkc  = (t & 3) * 4;
    const int swz  = (t & 3) * 8;

    for (int k0 = 0; k0 < 1024; k0 += 16) {
#pragma unroll
        for (int i = 0; i < 2; i++) {
            const int row = lrow + i * 64;
            float4 a = *(const float4*)(A + (size_t)(bm + row) * 1024 + k0 + lkc);
            float4 b = *(const float4*)(W + (size_t)(bn + row) * 1024 + k0 + lkc);
            const int sc = row ^ swz;
            As[lkc + 0][sc] = a.x; As[lkc + 1][sc] = a.y;
            As[lkc + 2][sc] = a.z; As[lkc + 3][sc] = a.w;
            Bs[lkc + 0][sc] = b.x; Bs[lkc + 1][sc] = b.y;
            Bs[lkc + 2][sc] = b.z; Bs[lkc + 3][sc] = b.w;
        }
        __syncthreads();
#pragma unroll
        for (int kk = 0; kk < 16; kk++) {
            const int sa = (kk >> 2) * 8;
            const int ca = tm ^ sa;
            const int cb = tn ^ sa;
            float a8[8];
            *(float4*)&a8[0] = *(const float4*)&As[kk][ca];
            *(float4*)&a8[4] = *(const float4*)&As[kk][ca + 4];
            float4 b0 = *(const float4*)&Bs[kk][cb];
            float4 b1 = *(const float4*)&Bs[kk][cb + 4];
            uint64_t b2[4];
            b2[0] = pk2(b0.x, b0.y); b2[1] = pk2(b0.z, b0.w);
            b2[2] = pk2(b1.x, b1.y); b2[3] = pk2(b1.z, b1.w);
#pragma unroll
            for (int i = 0; i < 8; i++) {
                const uint64_t ai = pk2(a8[i], a8[i]);
#pragma unroll
                for (int j = 0; j < 4; j++)
                    acc2[i][j] = fma2(ai, b2[j], acc2[i][j]);
            }
        }
        __syncthreads();
    }
#pragma unroll
    for (int i = 0; i < 8; i++) {
        float c[8];
#pragma unroll
        for (int j = 0; j < 4; j++) upk2(acc2[i][j], c[2*j], c[2*j+1]);
        float* cp = C + (size_t)(bm + tm + i) * 1024 + bn + tn;
        *(float4*)(cp)     = make_float4(c[0], c[1], c[2], c[3]);
        *(float4*)(cp + 4) = make_float4(c[4], c[5], c[6], c[7]);
    }
}
#endif

__device__ void gemm_impl(const float* __restrict__ A,
                          const float* __restrict__ W,
                          float* __restrict__ C, int vt)
{
#if HAS_TCGEN05
    extern __shared__ char smem[];
    const uint32_t sm_base = smem_u32(smem);
    const int t    = threadIdx.x;
    const int wid  = t >> 5;
    const int lid  = t & 31;
    const int rank = blockIdx.x & 1;          // cluster rank (cluster_dims x=2)
    const int bm   = blockIdx.y * GTM;
    const int bn   = (blockIdx.x >> 1) * GTN;
    const int am0  = bm + rank * 128;         // this CTA's A rows
    const int bn0  = bn + rank * 128;         // this CTA's B rows (N split)
    const uint32_t LM = sm_base + SM_MBAR;        // readiness, rank0's copies used
    const uint32_t MM = sm_base + SM_MBAR + 24;   // MMA-done (multicast), per CTA

    if (wid == 0) {
        asm volatile("tcgen05.alloc.cta_group::2.sync.aligned.shared::cta.b32 [%0], %1;"
                     :: "r"(sm_base + 0), "r"(256u) : "memory");
    }
    if (t == 0) {
#pragma unroll
        for (int i = 0; i < 3; i++) {
            mbar_init(LM + 8 * i, 2);     // one arrive from each CTA
            mbar_init(MM + 8 * i, 1);     // one multicast commit
        }
    }
    __syncthreads();
    CLUSTER_SYNC_();    // peer mbars initialized before any cluster arrive
    uint32_t tmem;
    asm volatile("ld.shared.b32 %0, [%1];" : "=r"(tmem) : "r"(sm_base + 0));

    g2_load_stage(sm_base, A, W, am0, bn0, 0, 0, t); cp_commit();
    g2_load_stage(sm_base, A, W, am0, bn0, 1, 1, t); cp_commit();
    g2_load_stage(sm_base, A, W, am0, bn0, 2, 2, t); cp_commit();

    for (int s = 0; s < NSTAGES; s++) {
        const int buf = s % 3;
        const int rem = NSTAGES - 1 - s;
        if (rem >= 2) cp_wait2();
        else if (rem == 1) cp_wait1();
        else cp_wait0();
        __syncthreads();

        if (t == 0) {
            asm volatile("fence.proxy.async;" ::: "memory");
            mbar_arrive_rank0(LM + 8 * buf);      // both CTAs signal rank0
        }
        if (rank == 0 && wid == 0) {
            if (elect1()) {
                mbar_waitc(LM + 8 * buf, (uint32_t)((s / 3) & 1));
                const uint32_t ab = sm_base + SM_TILES + buf * G2_BUFSTRIDE;
                const uint64_t ad = mk_desc(ab);
                const uint64_t bd = mk_desc(ab + G2_ABYTES);
#pragma unroll
                for (int c = 0; c < 4; c++)
                    mma_tf32_ss_cg2(tmem, ad + 2 * c, bd + 2 * c, IDESC_G2,
                                    (s > 0) || (c > 0));
                tc_commit_mc2(MM + 8 * buf);
            }
        }

        if (s + 3 < NSTAGES) {
            // buffer reuse: both CTAs wait MMA(s) done (local multicast copy)
            mbar_waitc(MM + 8 * buf, (uint32_t)((s / 3) & 1));
            g2_load_stage(sm_base, A, W, am0, bn0, s + 3, buf, t);
            cp_commit();
        }
    }

    // stage 31 -> MM[1], commit #11 -> phase 10, parity 0; chained waits.
    mbar_waitc(MM + 8 * ((NSTAGES - 1) % 3),
               (uint32_t)(((NSTAGES - 1) / 3) & 1));
    asm volatile("tcgen05.fence::after_thread_sync;" ::: "memory");

    // epilogue: this CTA's TMEM holds its 128 M-rows x 256 N-cols.
    // warp-group (wid>>2) takes a 128-col half, rows (wid&3)*32+lid.
    {
        const int lrow = (wid & 3) * 32 + lid;
        const int row  = bm + rank * 128 + lrow;
        const int cg0  = (wid >> 2) * 128;
        if (!vt) {
#pragma unroll
            for (int cc = 0; cc < 4; cc++) {
                uint32_t r[32];
                LDTM_X32(r, tmem + cg0 + cc * 32);
                asm volatile("tcgen05.wait::ld.sync.aligned;" ::: "memory");
                float* cp = C + (size_t)row * HALFD + bn + cg0 + cc * 32;
#pragma unroll
                for (int j = 0; j < 8; j++)
                    *(uint4*)(cp + 4 * j) = make_uint4(r[4*j], r[4*j+1], r[4*j+2], r[4*j+3]);
            }
        } else {
            // transposed V write: dst[(b*1024 + f) * 2048 + tok]
            const int tok  = row & (LEN - 1);
            const int bidx = row >> 11;
            float* dstb = C + (size_t)bidx * 1024 * LEN + tok;
#pragma unroll
            for (int cc = 0; cc < 4; cc++) {
                uint32_t r[32];
                LDTM_X32(r, tmem + cg0 + cc * 32);
                asm volatile("tcgen05.wait::ld.sync.aligned;" ::: "memory");
                const int f0 = bn + cg0 + cc * 32;
#pragma unroll
                for (int j = 0; j < 32; j++)
                    dstb[(size_t)(f0 + j) * LEN] = __uint_as_float(r[j]);
            }
        }
    }

    __syncthreads();
    if (t == 0) {
#pragma unroll
        for (int i = 0; i < 6; i++)
            asm volatile("mbarrier.inval.shared.b64 [%0];"
                         :: "r"(sm_base + SM_MBAR + 8 * i) : "memory");
    }
    __syncthreads();
    if (wid == 0) {
        asm volatile("tcgen05.relinquish_alloc_permit.cta_group::2.sync.aligned;");
        asm volatile("tcgen05.dealloc.cta_group::2.sync.aligned.b32 %0, %1;"
                     :: "r"(tmem), "r"(256u));
    }
    CLUSTER_SYNC_();
#else
    const int rank = blockIdx.x & 1;
    const int bm = blockIdx.y * GTM + rank * 128;
    const int bn = (blockIdx.x >> 1) * GTN;
    (void)vt;
#pragma unroll
    for (int jj = 0; jj < 2; jj++)
        gemm128_fb(A, W, C, bm, bn + jj * 128);
#endif
}

__global__ __launch_bounds__(256) __cluster_dims__(2, 1, 1) void qkv_gemm(
    const float* __restrict__ xa, const float* __restrict__ xb,
    const float* __restrict__ Wqa, const float* __restrict__ Wka, const float* __restrict__ Wva,
    const float* __restrict__ Wqb, const float* __restrict__ Wkb, const float* __restrict__ Wvb)
{
    const int z = blockIdx.z;
    const float* A = (z < 3) ? xa : xb;
    const float* W;
    float* C;
    int vt = 0;
    switch (z) {
        case 0: W = Wqa; C = g_qa; break;
        case 1: W = Wka; C = g_ka; break;
        case 2: W = Wva;
#if HAS_TCGEN05
            C = g_vaT; vt = 1;
#else
            C = g_va;
#endif
            break;
        case 3: W = Wqb; C = g_qb; break;
        case 4: W = Wkb; C = g_kb; break;
        default: W = Wvb;
#if HAS_TCGEN05
            C = g_vbT; vt = 1;
#else
            C = g_vb;
#endif
            break;
    }
    gemm_impl(A, W, C, vt);
}

__global__ __launch_bounds__(256) __cluster_dims__(2, 1, 1) void oproj_gemm(
    const float* __restrict__ Woa, const float* __restrict__ Wob)
{
    const int z = blockIdx.z;
    const float* A = z ? g_ob : g_oa;
    const float* W = z ? Wob  : Woa;
    float*       C = z ? g_pb : g_pa;
    gemm_impl(A, W, C, 0);
}

// ---------------------------------------------------------------------------
// V transpose: fallback-only (tcgen05 qkv writes transposed layout directly).
// ---------------------------------------------------------------------------
__global__ __launch_bounds__(256) void v_transpose()
{
#if !HAS_TCGEN05
    __shared__ float tile[32][33];
    const int branch = blockIdx.z >> 5;
    const int bh = blockIdx.z & 31;
    const int b = bh >> 4, h = bh & 15;
    const float* __restrict__ src = branch ? g_vb : g_va;
    float* __restrict__ dst = branch ? g_vbT : g_vaT;
    const int tok0 = blockIdx.x * 32, d0 = blockIdx.y * 32;
    const int tx = threadIdx.x, ty = threadIdx.y;
#pragma unroll
    for (int i = 0; i < 4; i++) {
        const int tok = tok0 + ty + i * 8;
        tile[ty + i * 8][tx] = src[(size_t)(b * 2048 + tok) * 1024 + h * 64 + d0 + tx];
    }
    __syncthreads();
#pragma unroll
    for (int i = 0; i < 4; i++) {
        const int d = d0 + ty + i * 8;
        dst[(size_t)bh * 64 * 2048 + (size_t)d * 2048 + tok0 + tx] = tile[tx][ty + i * 8];
    }
#endif
}

// ---------------------------------------------------------------------------
// tcgen05 flash cross-attention, pipelined (R6/R10-validated, unchanged).
// grid (16 q-tiles, 32 bh, 2 branches), 256 threads.
// TMEM: S0 cols [0,128), S1 [128,256), O [256,320).
// ---------------------------------------------------------------------------
#define A_MB1  8
#define A_MB2  16
#define A_LS   32
#define A_Q    2048
#define A_K0   (A_Q + 32768)
#define A_V0   (A_Q + 3 * 32768)
#define ATT_SMEM (A_Q + 6 * 32768)   // 198656

#define IDESC_ATT1 ((1u<<4)|(2u<<7)|(2u<<10)|(16u<<17)|(8u<<24))  // N=128, M=128
#define IDESC_ATT2 ((1u<<4)|(2u<<7)|(2u<<10)|(8u<<17)|(8u<<24))   // N=64,  M=128

#if HAS_TCGEN05
// [128 rows x 64 floats] K-major blocked atoms (16 atom-rows x 2 atom-cols)
__device__ __forceinline__ void att_load_qk(uint32_t base, const float* src,
                                            int row0, int col0, int t)
{
#pragma unroll
    for (int i = 0; i < 8; i++) {
        const int chunk = t + i * 256;
        const int r = chunk >> 4;
        const int c = (chunk & 15) * 4;
        const uint32_t off = (uint32_t)(((r >> 3) + (c >> 5) * 16) * 1024
                           + (r & 7) * 128 + (c & 31) * 4);
        cp16(base + SWZ(off), src + (size_t)(row0 + r) * HALFD + col0 + c);
    }
}
// [64 rows x 128 floats] K-major blocked atoms (8 atom-rows x 4 atom-cols)
__device__ __forceinline__ void att_load_vt(uint32_t base, const float* srcT,
                                            int kt, int t)
{
#pragma unroll
    for (int i = 0; i < 8; i++) {
        const int chunk = t + i * 256;
        const int r = chunk >> 5;
        const int c = (chunk & 31) * 4;
        const uint32_t off = (uint32_t)(((r >> 3) + (c >> 5) * 8) * 1024
                           + (r & 7) * 128 + (c & 31) * 4);
        cp16(base + SWZ(off), srcT + (size_t)r * LEN + kt * 128 + c);
    }
}

__device__ __forceinline__ void att_gemm1(uint32_t sm, uint32_t s_t, int kbuf)
{
    const uint64_t ad = mk_desc(sm + A_Q);
    const uint64_t bd = mk_desc(sm + A_K0 + kbuf * 32768);
#pragma unroll
    for (int kc = 0; kc < 8; kc++) {
        const uint32_t u = (kc >> 2) * 1024 + (kc & 3) * 2;
        mma_tf32_ss(s_t, ad + u, bd + u, IDESC_ATT1, kc > 0);
    }
    tc_commit(sm + A_MB1);
}
#endif

__global__ __launch_bounds__(256) void attn_kernel()
{
#if HAS_TCGEN05
    extern __shared__ char smem[];
    const uint32_t sm = smem_u32(smem);
    const int t = threadIdx.x;
    const int w = t >> 5;
    const int lane = t & 31;
    const int branch = blockIdx.z;
    const int bh = blockIdx.y;
    const int b = bh >> 4, h = bh & 15;
    const int tq = blockIdx.x;

    const float* __restrict__ Q  = branch ? g_qb  : g_qa;
    const float* __restrict__ K  = branch ? g_ka  : g_kb;
    const float* __restrict__ VT = branch ? g_vaT : g_vbT;
    float* __restrict__ O        = branch ? g_ob  : g_oa;
    const float* vt_slice = VT + (size_t)bh * HD * LEN;

    if (w == 0) {
        asm volatile("tcgen05.alloc.cta_group::1.sync.aligned.shared::cta.b32 [%0], %1;"
                     :: "r"(sm + 0), "r"(512u) : "memory");
    }
    if (t == 0) { mbar_init(sm + A_MB1, 1); mbar_init(sm + A_MB2, 1); }
    __syncthreads();
    uint32_t tmem;
    asm volatile("ld.shared.b32 %0, [%1];" : "=r"(tmem) : "r"(sm + 0));
    const uint32_t O_t = tmem + 256;

    const int qrow0 = b * LEN + tq * 128;
    const int krow0 = b * LEN;
    const uint32_t warp_off = (uint32_t)(w & 3) << 21;

    att_load_qk(sm + A_Q,  Q, qrow0, h * HD, t);
    att_load_qk(sm + A_K0, K, krow0, h * HD, t);
    att_load_vt(sm + A_V0, vt_slice, 0, t);
    cp_commit();
    att_load_qk(sm + A_K0 + 32768, K, krow0 + 128, h * HD, t);
    att_load_vt(sm + A_V0 + 32768, vt_slice, 1, t);
    cp_commit();

    cp_wait1();
    __syncthreads();
    if (w == 0) {
        asm volatile("fence.proxy.async.shared::cta;" ::: "memory");
        if (elect1()) att_gemm1(sm, tmem + 0, 0);      // GEMM1(0) -> S0
    }

    const float inv_scale = 0.08838834764831845f;  // 1/sqrt(128)
    float lsum = 0.f;
    const int cb = (w >> 2) * 64;   // this warp's score-column half

    for (int kt = 0; kt < 16; kt++) {
        const uint32_t S_t = tmem + (kt & 1) * 128;

        mbar_wait(sm + A_MB1, kt & 1);
        asm volatile("tcgen05.fence::after_thread_sync;" ::: "memory");

        if (kt + 1 < 16) {
            cp_wait0();
            if (kt >= 1) mbar_wait(sm + A_MB2, (kt - 1) & 1);
            __syncthreads();
            if (w == 0) {
                asm volatile("fence.proxy.async.shared::cta;" ::: "memory");
                if (elect1())
                    att_gemm1(sm, tmem + ((kt + 1) & 1) * 128, (kt + 1) & 1);
            }
            if (kt + 2 < 16) {
                att_load_qk(sm + A_K0 + (kt & 1) * 32768, K,
                            krow0 + (kt + 2) * 128, h * HD, t);
                att_load_vt(sm + A_V0 + ((kt + 2) % 3) * 32768, vt_slice, kt + 2, t);
                cp_commit();
            }
        }

        {
            uint32_t r0[32], r1[32];
            LDTM_X32(r0, S_t + cb + warp_off);
            LDTM_X32(r1, S_t + cb + 32 + warp_off);
            asm volatile("tcgen05.wait::ld.sync.aligned;" ::: "memory");
            float part = 0.f;
#pragma unroll
            for (int j = 0; j < 32; j++) {
                float p = __expf(__uint_as_float(r0[j]) * inv_scale);
                part += p;
                r0[j] = __float_as_uint(p);
            }
#pragma unroll
            for (int j = 0; j < 32; j++) {
                float p = __expf(__uint_as_float(r1[j]) * inv_scale);
                part += p;
                r1[j] = __float_as_uint(p);
            }
            lsum += part;
            STTM_X32(S_t + cb + warp_off, r0);
            STTM_X32(S_t + cb + 32 + warp_off, r1);
            asm volatile("tcgen05.wait::st.sync.aligned;" ::: "memory");
            asm volatile("tcgen05.fence::before_thread_sync;" ::: "memory");
        }
        __syncthreads();

        if (w == 0) {
            if (elect1()) {
                asm volatile("tcgen05.fence::after_thread_sync;" ::: "memory");
                const uint64_t bd = mk_desc(sm + A_V0 + (kt % 3) * 32768);
#pragma unroll
                for (int kc = 0; kc < 16; kc++) {
                    const uint64_t u = (kc >> 2) * 512 + (kc & 3) * 2;
                    mma_tf32_ts(O_t, S_t + kc * 8, bd + u, IDESC_ATT2,
                                (kt > 0) || (kc > 0));
                }
                tc_commit(sm + A_MB2);
            }
        }
    }

    float* ls = (float*)(smem + A_LS);
    const int r = (w & 3) * 32 + lane;
    ls[(w >> 2) * 128 + r] = lsum;
    __syncthreads();
    const float inv_l = 1.f / (ls[r] + ls[128 + r]);

    mbar_wait(sm + A_MB2, 1);
    asm volatile("tcgen05.fence::after_thread_sync;" ::: "memory");

    {
        const int c0 = (w >> 2) * 32;
        uint32_t rr[32];
        LDTM_X32(rr, O_t + c0 + warp_off);
        asm volatile("tcgen05.wait::ld.sync.aligned;" ::: "memory");
        float* op = O + (size_t)(qrow0 + r) * HALFD + h * HD + c0;
#pragma unroll
        for (int j = 0; j < 8; j++) {
            float4 v;
            v.x = __uint_as_float(rr[4*j])   * inv_l;
            v.y = __uint_as_float(rr[4*j+1]) * inv_l;
            v.z = __uint_as_float(rr[4*j+2]) * inv_l;
            v.w = __uint_as_float(rr[4*j+3]) * inv_l;
            *(float4*)(op + 4 * j) = v;
        }
    }

    __syncthreads();
    if (t == 0) {
        asm volatile("mbarrier.inval.shared.b64 [%0];" :: "r"(sm + A_MB1) : "memory");
        asm volatile("mbarrier.inval.shared.b64 [%0];" :: "r"(sm + A_MB2) : "memory");
    }
    __syncthreads();
    if (w == 0) {
        asm volatile("tcgen05.relinquish_alloc_permit.cta_group::1.sync.aligned;");
        asm volatile("tcgen05.dealloc.cta_group::1.sync.aligned.b32 %0, %1;"
                     :: "r"(tmem), "r"(512u));
    }
#else
    // ---------------- SIMT f32x2 fallback ----------------
    const int branch = blockIdx.z;
    const float* __restrict__ Q = branch ? g_qb : g_qa;
    const float* __restrict__ K = branch ? g_ka : g_kb;
    const float* __restrict__ V = branch ? g_va : g_vb;
    float* __restrict__ O       = branch ? g_ob : g_oa;

    const int bh = blockIdx.y;
    const int b  = bh >> 4;
    const int h  = bh & 15;
    const size_t base = (size_t)b * LEN * HALFD + (size_t)h * HD;

    const int t    = threadIdx.x;
    const int qi   = t >> 1;
    const int half = t & 1;
    const int l    = blockIdx.x * 128 + qi;

    __shared__ __align__(16) float Ks[64][68];
    __shared__ __align__(16) float Vs[64][68];

    const float* qp = Q + base + (size_t)l * HALFD + 4 * half;
    uint64_t q2[16];
    {
        const uint64_t* qd = (const uint64_t*)qp;
#pragma unroll
        for (int j = 0; j < 8; j++) {
            q2[2*j]   = qd[4*j];
            q2[2*j+1] = qd[4*j + 1];
        }
    }

    uint64_t acc2[16];
#pragma unroll
    for (int j = 0; j < 16; j++) acc2[j] = 0ull;
    float mval = -1e30f, lsum = 0.f;
    const float inv_scale = 0.08838834764831845f;

    const int lr = t >> 2;
    const int lc = (t & 3) * 16;

    for (int kt = 0; kt < LEN; kt += 64) {
        __syncthreads();
        {
            const float* kp = K + base + (size_t)(kt + lr) * HALFD + lc;
            const float* vp = V + base + (size_t)(kt + lr) * HALFD + lc;
#pragma unroll
            for (int j = 0; j < 4; j++) {
                *(float4*)&Ks[lr][lc + 4 * j] = *(const float4*)(kp + 4 * j);
                *(float4*)&Vs[lr][lc + 4 * j] = *(const float4*)(vp + 4 * j);
            }
        }
        __syncthreads();

#pragma unroll 2
        for (int k = 0; k < 64; k++) {
            const uint64_t* krow = (const uint64_t*)(&Ks[k][4 * half]);
            uint64_t s2 = 0ull;
#pragma unroll
            for (int j = 0; j < 8; j++) {
                s2 = fma2(q2[2*j],   krow[4*j],     s2);
                s2 = fma2(q2[2*j+1], krow[4*j + 1], s2);
            }
            float slo, shi;
            upk2(s2, slo, shi);
            float s = slo + shi;
            s += __shfl_xor_sync(0xffffffffu, s, 1);
            s *= inv_scale;

            float p;
            if (s > mval) {
                const float cfac = __expf(mval - s);
                mval = s;
                lsum *= cfac;
                const uint64_t c2 = pk2(cfac, cfac);
#pragma unroll
                for (int j = 0; j < 16; j++) acc2[j] = mul2(acc2[j], c2);
                p = 1.f;
            } else {
                p = __expf(s - mval);
            }
            lsum += p;

            const uint64_t p2 = pk2(p, p);
            const uint64_t* vrow = (const uint64_t*)(&Vs[k][4 * half]);
#pragma unroll
            for (int j = 0; j < 8; j++) {
                acc2[2*j]   = fma2(p2, vrow[4*j],     acc2[2*j]);
                acc2[2*j+1] = fma2(p2, vrow[4*j + 1], acc2[2*j+1]);
            }
        }
    }

    const float inv_l = 1.f / lsum;
    const uint64_t inv2 = pk2(inv_l, inv_l);
    uint64_t* od = (uint64_t*)(O + base + (size_t)l * HALFD + 4 * half);
#pragma unroll
    for (int j = 0; j < 8; j++) {
        od[4*j]     = mul2(acc2[2*j],   inv2);
        od[4*j + 1] = mul2(acc2[2*j+1], inv2);
    }
#endif
}

// ---------------------------------------------------------------------------
// Residual + LayerNorm.
// ---------------------------------------------------------------------------
__global__ __launch_bounds__(256) void ln_kernel(
    const float* __restrict__ xa, const float* __restrict__ xb,
    const float* __restrict__ ga, const float* __restrict__ ba,
    const float* __restrict__ gb, const float* __restrict__ bb,
    float* __restrict__ out)
{
    const int row   = blockIdx.x;
    const int which = blockIdx.y;
    const float* x     = which ? xb   : xa;
    const float* p     = which ? g_pb : g_pa;
    const float* gamma = which ? gb   : ga;
    const float* beta  = which ? bb   : ba;
    float* o = out + (size_t)which * ELEMS + (size_t)row * HALFD;

    const int t = threadIdx.x;
    float4 xv = ((const float4*)(x + (size_t)row * HALFD))[t];
    float4 pv = ((const float4*)(p + (size_t)row * HALFD))[t];
    float4 sv = make_float4(xv.x + pv.x, xv.y + pv.y, xv.z + pv.z, xv.w + pv.w);

    float s  = sv.x + sv.y + sv.z + sv.w;
    float sq = sv.x * sv.x + sv.y * sv.y + sv.z * sv.z + sv.w * sv.w;
#pragma unroll
    for (int off = 16; off > 0; off >>= 1) {
        s  += __shfl_xor_sync(0xffffffffu, s,  off);
        sq += __shfl_xor_sync(0xffffffffu, sq, off);
    }
    __shared__ float ss[8], ssq[8];
    if ((t & 31) == 0) { ss[t >> 5] = s; ssq[t >> 5] = sq; }
    __syncthreads();
    float tot = 0.f, totq = 0.f;
#pragma unroll
    for (int i = 0; i < 8; i++) { tot += ss[i]; totq += ssq[i]; }

    const float mean = tot * (1.f / HALFD);
    const float var  = totq * (1.f / HALFD) - mean * mean;
    const float rstd = rsqrtf(var + 1e-5f);

    float4 g4 = ((const float4*)gamma)[t];
    float4 b4 = ((const float4*)beta)[t];
    float4 rr;
    rr.x = (sv.x - mean) * rstd * g4.x + b4.x;
    rr.y = (sv.y - mean) * rstd * g4.y + b4.y;
    rr.z = (sv.z - mean) * rstd * g4.z + b4.z;
    rr.w = (sv.w - mean) * rstd * g4.w + b4.w;
    ((float4*)o)[t] = rr;
}

// ---------------------------------------------------------------------------
extern "C" void kernel_launch(void* const* d_in, const int* in_sizes, int n_in,
                              void* d_out, int out_size)
{
    const float* x_a  = (const float*)d_in[0];
    const float* x_b  = (const float*)d_in[1];
    const float* Wq_a = (const float*)d_in[2];
    const float* Wq_b = (const float*)d_in[3];
    const float* Wk_a = (const float*)d_in[4];
    const float* Wk_b = (const float*)d_in[5];
    const float* Wv_a = (const float*)d_in[6];
    const float* Wv_b = (const float*)d_in[7];
    const float* Wo_a = (const float*)d_in[8];
    const float* Wo_b = (const float*)d_in[9];
    const float* ga   = (const float*)d_in[10];
    const float* ba   = (const float*)d_in[11];
    const float* gb   = (const float*)d_in[12];
    const float* bb   = (const float*)d_in[13];
    float* out = (float*)d_out;

    cudaFuncSetAttribute(qkv_gemm, cudaFuncAttributeMaxDynamicSharedMemorySize,
                         SMEM_GEMM_TOTAL);
    cudaFuncSetAttribute(oproj_gemm, cudaFuncAttributeMaxDynamicSharedMemorySize,
                         SMEM_GEMM_TOTAL);
    cudaFuncSetAttribute(attn_kernel, cudaFuncAttributeMaxDynamicSharedMemorySize,
                         ATT_SMEM);

    // grid.x = 2 ranks x (HALFD/GTN) n-tiles; cluster dims (2,1,1)
    dim3 gq(2 * (HALFD / GTN), MROWS / GTM, 6);   // (8, 16, 6)
    qkv_gemm<<<gq, 256, SMEM_GEMM_TOTAL>>>(x_a, x_b, Wq_a, Wk_a, Wv_a,
                                           Wq_b, Wk_b, Wv_b);

    dim3 gt(LEN / 32, HD / 32, 64);
    v_transpose<<<gt, dim3(32, 8)>>>();   // no-op on the tcgen05 cubin

    dim3 gat(LEN / 128, BN * NH, 2);
    attn_kernel<<<gat, 256, ATT_SMEM>>>();

    dim3 go(2 * (HALFD / GTN), MROWS / GTM, 2);   // (8, 16, 2)
    oproj_gemm<<<go, 256, SMEM_GEMM_TOTAL>>>(Wo_a, Wo_b);

    dim3 gl(MROWS, 2);
    ln_kernel<<<gl, 256>>>(x_a, x_b, ga, ba, gb, bb, out);
}

// round 12
// speedup vs baseline: 1.8417x; 1.8417x over previous
#include <cuda_runtime.h>
#include <cstdint>
#include <math.h>

// Problem constants
#define BN    2
#define LEN   2048
#define HALFD 1024
#define NH    16
#define HD    64
#define MROWS (BN * LEN)        // 4096
#define ELEMS (MROWS * HALFD)   // 4194304 per tensor

// Scratch (device globals: no allocation allowed)
__device__ float g_qa[ELEMS];
__device__ float g_ka[ELEMS];
__device__ float g_va[ELEMS];
__device__ float g_qb[ELEMS];
__device__ float g_kb[ELEMS];
__device__ float g_vb[ELEMS];
__device__ float g_oa[ELEMS];
__device__ float g_ob[ELEMS];
__device__ float g_pa[ELEMS];
__device__ float g_pb[ELEMS];
__device__ float g_vaT[ELEMS];   // [bh][64][2048] transposed V, branch a
__device__ float g_vbT[ELEMS];   // [bh][64][2048] transposed V, branch b

#if defined(__CUDA_ARCH__) && (defined(__CUDA_ARCH_FEAT_SM103_ALL) || \
    defined(__CUDA_ARCH_FEAT_SM100_ALL) || defined(__CUDA_ARCH_FEAT_SM101_ALL))
#define HAS_TCGEN05 1
#else
#define HAS_TCGEN05 0
#endif

// ---------------------------------------------------------------------------
// packed f32x2 helpers (legal in plain pass)
// ---------------------------------------------------------------------------
__device__ __forceinline__ uint64_t pk2(float lo, float hi) {
    uint64_t r;
    asm("mov.b64 %0, {%1, %2};" : "=l"(r) : "f"(lo), "f"(hi));
    return r;
}
__device__ __forceinline__ void upk2(uint64_t v, float& lo, float& hi) {
    asm("mov.b64 {%0, %1}, %2;" : "=f"(lo), "=f"(hi) : "l"(v));
}
__device__ __forceinline__ uint64_t fma2(uint64_t a, uint64_t b, uint64_t c) {
    uint64_t d;
    asm("fma.rn.f32x2 %0, %1, %2, %3;" : "=l"(d) : "l"(a), "l"(b), "l"(c));
    return d;
}
__device__ __forceinline__ uint64_t mul2(uint64_t a, uint64_t b) {
    uint64_t d;
    asm("mul.rn.f32x2 %0, %1, %2;" : "=l"(d) : "l"(a), "l"(b));
    return d;
}

// ---------------------------------------------------------------------------
// common asm helpers
// ---------------------------------------------------------------------------
#define SWZ(off) ((off) ^ (((off) >> 3) & 0x70))

__device__ __forceinline__ uint32_t smem_u32(const void* p) {
    uint32_t a;
    asm("{ .reg .u64 t; cvta.to.shared.u64 t, %1; cvt.u32.u64 %0, t; }"
        : "=r"(a) : "l"(p));
    return a;
}
__device__ __forceinline__ void cp16(uint32_t dst, const void* src) {
    asm volatile("cp.async.cg.shared.global [%0], [%1], 16;" :: "r"(dst), "l"(src));
}
__device__ __forceinline__ void cp_commit() {
    asm volatile("cp.async.commit_group;" ::: "memory");
}
__device__ __forceinline__ void cp_wait2() {
    asm volatile("cp.async.wait_group 2;" ::: "memory");
}
__device__ __forceinline__ void cp_wait1() {
    asm volatile("cp.async.wait_group 1;" ::: "memory");
}
__device__ __forceinline__ void cp_wait0() {
    asm volatile("cp.async.wait_group 0;" ::: "memory");
}

#if HAS_TCGEN05
__device__ __forceinline__ uint32_t elect1() {
    uint32_t p;
    asm volatile("{ .reg .pred p; elect.sync _|p, 0xFFFFFFFF; selp.b32 %0,1,0,p; }"
                 : "=r"(p));
    return p;
}
__device__ __forceinline__ void mbar_init(uint32_t a, uint32_t cnt) {
    asm volatile("mbarrier.init.shared.b64 [%0], %1;" :: "r"(a), "r"(cnt) : "memory");
}
__device__ __forceinline__ void mbar_wait(uint32_t a, uint32_t par) {
    asm volatile(
        "{\n\t.reg .pred P;\n"
        "W_%=:\n\t"
        "mbarrier.try_wait.parity.acquire.cta.shared::cta.b64 P, [%0], %1, 0x989680;\n\t"
        "@!P bra W_%=;\n\t}"
        :: "r"(a), "r"(par) : "memory");
}
__device__ __forceinline__ void tc_commit(uint32_t mbar) {
    asm volatile(
        "tcgen05.commit.cta_group::1.mbarrier::arrive::one.shared::cluster.b64 [%0];"
        :: "r"(mbar) : "memory");
}
__device__ __forceinline__ uint64_t mk_desc(uint32_t addr) {
    const uint64_t base = (uint64_t(2) << 61) | (uint64_t(1) << 46)
                        | (uint64_t(64) << 32) | (uint64_t(1) << 16);
    return base | ((uint64_t)(addr >> 4) & 0x3FFF);
}
__device__ __forceinline__ void mma_tf32_ss(uint32_t d, uint64_t ad, uint64_t bd,
                                            uint32_t idesc, uint32_t en) {
    asm volatile(
        "{\n\t.reg .pred p;\n\t"
        "setp.ne.u32 p, %4, 0;\n\t"
        "tcgen05.mma.cta_group::1.kind::tf32 [%0], %1, %2, %3, {%5,%5,%5,%5}, p;\n\t}"
        :: "r"(d), "l"(ad), "l"(bd), "r"(idesc), "r"(en), "r"(0u)
        : "memory");
}
__device__ __forceinline__ void mma_tf32_ts(uint32_t d, uint32_t a, uint64_t bd,
                                            uint32_t idesc, uint32_t en) {
    asm volatile(
        "{\n\t.reg .pred p;\n\t"
        "setp.ne.u32 p, %4, 0;\n\t"
        "tcgen05.mma.cta_group::1.kind::tf32 [%0], [%1], %2, %3, {%5,%5,%5,%5}, p;\n\t}"
        :: "r"(d), "r"(a), "l"(bd), "r"(idesc), "r"(en), "r"(0u)
        : "memory");
}

#define LDTM_X32(r, addr) \
    asm volatile( \
        "tcgen05.ld.sync.aligned.32x32b.x32.b32 " \
        "{%0,%1,%2,%3,%4,%5,%6,%7,%8,%9,%10,%11,%12,%13,%14,%15," \
        "%16,%17,%18,%19,%20,%21,%22,%23,%24,%25,%26,%27,%28,%29,%30,%31}, [%32];" \
        : "=r"((r)[0]), "=r"((r)[1]), "=r"((r)[2]), "=r"((r)[3]), \
          "=r"((r)[4]), "=r"((r)[5]), "=r"((r)[6]), "=r"((r)[7]), \
          "=r"((r)[8]), "=r"((r)[9]), "=r"((r)[10]), "=r"((r)[11]), \
          "=r"((r)[12]), "=r"((r)[13]), "=r"((r)[14]), "=r"((r)[15]), \
          "=r"((r)[16]), "=r"((r)[17]), "=r"((r)[18]), "=r"((r)[19]), \
          "=r"((r)[20]), "=r"((r)[21]), "=r"((r)[22]), "=r"((r)[23]), \
          "=r"((r)[24]), "=r"((r)[25]), "=r"((r)[26]), "=r"((r)[27]), \
          "=r"((r)[28]), "=r"((r)[29]), "=r"((r)[30]), "=r"((r)[31]) \
        : "r"(addr))

#define STTM_X32(addr, r) \
    asm volatile( \
        "tcgen05.st.sync.aligned.32x32b.x32.b32 [%0], " \
        "{%1,%2,%3,%4,%5,%6,%7,%8,%9,%10,%11,%12,%13,%14,%15,%16," \
        "%17,%18,%19,%20,%21,%22,%23,%24,%25,%26,%27,%28,%29,%30,%31,%32};" \
        :: "r"(addr), \
           "r"((r)[0]), "r"((r)[1]), "r"((r)[2]), "r"((r)[3]), \
           "r"((r)[4]), "r"((r)[5]), "r"((r)[6]), "r"((r)[7]), \
           "r"((r)[8]), "r"((r)[9]), "r"((r)[10]), "r"((r)[11]), \
           "r"((r)[12]), "r"((r)[13]), "r"((r)[14]), "r"((r)[15]), \
           "r"((r)[16]), "r"((r)[17]), "r"((r)[18]), "r"((r)[19]), \
           "r"((r)[20]), "r"((r)[21]), "r"((r)[22]), "r"((r)[23]), \
           "r"((r)[24]), "r"((r)[25]), "r"((r)[26]), "r"((r)[27]), \
           "r"((r)[28]), "r"((r)[29]), "r"((r)[30]), "r"((r)[31]) \
        : "memory")
#endif  // HAS_TCGEN05

// ---------------------------------------------------------------------------
// Projection GEMM (R6/R10-validated): C[m,n] = sum_k A[m,k]*W[n,k].
// Tile 256x256 (two M=128 MMA chains -> TMEM D0 cols 0-255, D1 256-511),
// K staged 32 floats, 3-deep cp.async pipeline, rotating per-buffer mbars.
// vt=1 epilogue writes V directly in [bh][d][tok] transposed layout.
// ---------------------------------------------------------------------------
#define GTM 256
#define GTN 256
#define KSTEP 32
#define NSTAGES (HALFD / KSTEP)     // 32
#define G_NBUF 3
#define G_ABYTES  32768             // 256 rows x 128B
#define G_BUFSTRIDE 65536
#define SM_MBAR  8
#define SM_TILES 1024
#define SMEM_GEMM_TOTAL (SM_TILES + G_NBUF * G_BUFSTRIDE)   // 197632

// per-MMA idesc: M=128, N=256, tf32
#define IDESC_G ((1u<<4)|(2u<<7)|(2u<<10)|((GTN/8)<<17)|(8u<<24))

__device__ __forceinline__ void g_load_stage(uint32_t sm_base,
                                             const float* __restrict__ A,
                                             const float* __restrict__ W,
                                             int bm, int bn, int s, int buf, int t)
{
    const int k0  = s * KSTEP;
    const int rb  = t >> 3;        // 0..31
    const int c16 = (t & 7);       // 16B chunk within 128B row
    const uint32_t abase = sm_base + SM_TILES + buf * G_BUFSTRIDE;
    const uint32_t bbase = abase + G_ABYTES;
#pragma unroll
    for (int i = 0; i < 8; i++) {
        const int row = i * 32 + rb;
        const uint32_t off = row * 128 + c16 * 16;
        cp16(abase + SWZ(off), A + (size_t)(bm + row) * HALFD + k0 + c16 * 4);
    }
#pragma unroll
    for (int i = 0; i < 8; i++) {
        const int row = i * 32 + rb;
        const uint32_t off = row * 128 + c16 * 16;
        cp16(bbase + SWZ(off), W + (size_t)(bn + row) * HALFD + k0 + c16 * 4);
    }
}

#if !HAS_TCGEN05
// SIMT f32x2 128x128 sub-tile (fallback only)
__device__ void gemm128_fb(const float* __restrict__ A,
                           const float* __restrict__ W,
                           float* __restrict__ C, int bm, int bn)
{
    __shared__ float As[16][128];
    __shared__ float Bs[16][128];
    const int t  = threadIdx.x;
    const int tm = (t >> 4) * 8;
    const int tn = (t & 15) * 8;

    uint64_t acc2[8][4];
#pragma unroll
    for (int i = 0; i < 8; i++)
#pragma unroll
        for (int j = 0; j < 4; j++) acc2[i][j] = 0ull;

    const int lrow = t >> 2;
    const int lkc  = (t & 3) * 4;
    const int swz  = (t & 3) * 8;

    for (int k0 = 0; k0 < 1024; k0 += 16) {
#pragma unroll
        for (int i = 0; i < 2; i++) {
            const int row = lrow + i * 64;
            float4 a = *(const float4*)(A + (size_t)(bm + row) * 1024 + k0 + lkc);
            float4 b = *(const float4*)(W + (size_t)(bn + row) * 1024 + k0 + lkc);
            const int sc = row ^ swz;
            As[lkc + 0][sc] = a.x; As[lkc + 1][sc] = a.y;
            As[lkc + 2][sc] = a.z; As[lkc + 3][sc] = a.w;
            Bs[lkc + 0][sc] = b.x; Bs[lkc + 1][sc] = b.y;
            Bs[lkc + 2][sc] = b.z; Bs[lkc + 3][sc] = b.w;
        }
        __syncthreads();
#pragma unroll
        for (int kk = 0; kk < 16; kk++) {
            const int sa = (kk >> 2) * 8;
            const int ca = tm ^ sa;
            const int cb = tn ^ sa;
            float a8[8];
            *(float4*)&a8[0] = *(const float4*)&As[kk][ca];
            *(float4*)&a8[4] = *(const float4*)&As[kk][ca + 4];
            float4 b0 = *(const float4*)&Bs[kk][cb];
            float4 b1 = *(const float4*)&Bs[kk][cb + 4];
            uint64_t b2[4];
            b2[0] = pk2(b0.x, b0.y); b2[1] = pk2(b0.z, b0.w);
            b2[2] = pk2(b1.x, b1.y); b2[3] = pk2(b1.z, b1.w);
#pragma unroll
            for (int i = 0; i < 8; i++) {
                const uint64_t ai = pk2(a8[i], a8[i]);
#pragma unroll
                for (int j = 0; j < 4; j++)
                    acc2[i][j] = fma2(ai, b2[j], acc2[i][j]);
            }
        }
        __syncthreads();
    }
#pragma unroll
    for (int i = 0; i < 8; i++) {
        float c[8];
#pragma unroll
        for (int j = 0; j < 4; j++) upk2(acc2[i][j], c[2*j], c[2*j+1]);
        float* cp = C + (size_t)(bm + tm + i) * 1024 + bn + tn;
        *(float4*)(cp)     = make_float4(c[0], c[1], c[2], c[3]);
        *(float4*)(cp + 4) = make_float4(c[4], c[5], c[6], c[7]);
    }
}
#endif

__device__ void gemm_impl(const float* __restrict__ A,
                          const float* __restrict__ W,
                          float* __restrict__ C, int vt)
{
#if HAS_TCGEN05
    extern __shared__ char smem[];
    const uint32_t sm_base = smem_u32(smem);
    const int t   = threadIdx.x;
    const int wid = t >> 5;
    const int lid = t & 31;
    const int bm  = blockIdx.y * GTM;
    const int bn  = blockIdx.x * GTN;

    if (wid == 0) {
        asm volatile("tcgen05.alloc.cta_group::1.sync.aligned.shared::cta.b32 [%0], %1;"
                     :: "r"(sm_base + 0), "r"(512u) : "memory");
    }
    if (t == 0) {
        mbar_init(sm_base + SM_MBAR + 0, 1);
        mbar_init(sm_base + SM_MBAR + 8, 1);
        mbar_init(sm_base + SM_MBAR + 16, 1);
    }
    __syncthreads();
    uint32_t tmem;
    asm volatile("ld.shared.b32 %0, [%1];" : "=r"(tmem) : "r"(sm_base + 0));

    g_load_stage(sm_base, A, W, bm, bn, 0, 0, t); cp_commit();
    g_load_stage(sm_base, A, W, bm, bn, 1, 1, t); cp_commit();
    g_load_stage(sm_base, A, W, bm, bn, 2, 2, t); cp_commit();

    for (int s = 0; s < NSTAGES; s++) {
        const int buf = s % 3;
        const int rem = NSTAGES - 1 - s;
        if (rem >= 2) cp_wait2();
        else if (rem == 1) cp_wait1();
        else cp_wait0();
        __syncthreads();

        if (wid == 0) {
            asm volatile("fence.proxy.async.shared::cta;" ::: "memory");
            if (elect1()) {
                const uint32_t ab = sm_base + SM_TILES + buf * G_BUFSTRIDE;
                const uint64_t ad0 = mk_desc(ab);
                const uint64_t ad1 = mk_desc(ab + 16384);
                const uint64_t bd  = mk_desc(ab + G_ABYTES);
#pragma unroll
                for (int c = 0; c < 4; c++) {
                    const uint32_t en = (s > 0) || (c > 0);
                    mma_tf32_ss(tmem,       ad0 + 2 * c, bd + 2 * c, IDESC_G, en);
                    mma_tf32_ss(tmem + 256, ad1 + 2 * c, bd + 2 * c, IDESC_G, en);
                }
                tc_commit(sm_base + SM_MBAR + 8 * buf);
            }
        }

        if (s + 3 < NSTAGES) {
            mbar_wait(sm_base + SM_MBAR + 8 * buf, (uint32_t)((s / 3) & 1));
            g_load_stage(sm_base, A, W, bm, bn, s + 3, buf, t);
            cp_commit();
        }
    }

    // stage 31 committed to mbar[1] as commit #11 there -> phase 10, parity 0.
    mbar_wait(sm_base + SM_MBAR + 8 * ((NSTAGES - 1) % 3),
              (uint32_t)(((NSTAGES - 1) / 3) & 1));
    asm volatile("tcgen05.fence::after_thread_sync;" ::: "memory");

    {
        const int dtile = wid >> 2;
        const int row = bm + dtile * 128 + (wid & 3) * 32 + lid;
        if (!vt) {
#pragma unroll
            for (int cc = 0; cc < 8; cc++) {
                uint32_t r[32];
                LDTM_X32(r, tmem + dtile * 256 + cc * 32);
                asm volatile("tcgen05.wait::ld.sync.aligned;" ::: "memory");
                float* cp = C + (size_t)row * HALFD + bn + cc * 32;
#pragma unroll
                for (int j = 0; j < 8; j++)
                    *(uint4*)(cp + 4 * j) = make_uint4(r[4*j], r[4*j+1], r[4*j+2], r[4*j+3]);
            }
        } else {
            // transposed V write: dst[(b*1024 + f) * 2048 + tok],
            // f = bn + cc*32 + j, tok = row & 2047, b = row >> 11.
            const int tok = row & (LEN - 1);
            const int bidx = row >> 11;
            float* dstb = C + (size_t)bidx * 1024 * LEN + tok;
#pragma unroll
            for (int cc = 0; cc < 8; cc++) {
                uint32_t r[32];
                LDTM_X32(r, tmem + dtile * 256 + cc * 32);
                asm volatile("tcgen05.wait::ld.sync.aligned;" ::: "memory");
                const int f0 = bn + cc * 32;
#pragma unroll
                for (int j = 0; j < 32; j++)
                    dstb[(size_t)(f0 + j) * LEN] = __uint_as_float(r[j]);
            }
        }
    }

    __syncthreads();
    if (t == 0) {
        asm volatile("mbarrier.inval.shared.b64 [%0];" :: "r"(sm_base + SM_MBAR + 0) : "memory");
        asm volatile("mbarrier.inval.shared.b64 [%0];" :: "r"(sm_base + SM_MBAR + 8) : "memory");
        asm volatile("mbarrier.inval.shared.b64 [%0];" :: "r"(sm_base + SM_MBAR + 16) : "memory");
    }
    __syncthreads();
    if (wid == 0) {
        asm volatile("tcgen05.relinquish_alloc_permit.cta_group::1.sync.aligned;");
        asm volatile("tcgen05.dealloc.cta_group::1.sync.aligned.b32 %0, %1;"
                     :: "r"(tmem), "r"(512u));
    }
#else
    (void)vt;
    const int bm = blockIdx.y * GTM;
    const int bn = blockIdx.x * GTN;
#pragma unroll
    for (int ii = 0; ii < 2; ii++)
#pragma unroll
        for (int jj = 0; jj < 2; jj++)
            gemm128_fb(A, W, C, bm + ii * 128, bn + jj * 128);
#endif
}

__global__ __launch_bounds__(256) void qkv_gemm(
    const float* __restrict__ xa, const float* __restrict__ xb,
    const float* __restrict__ Wqa, const float* __restrict__ Wka, const float* __restrict__ Wva,
    const float* __restrict__ Wqb, const float* __restrict__ Wkb, const float* __restrict__ Wvb)
{
    const int z = blockIdx.z;
    const float* A = (z < 3) ? xa : xb;
    const float* W;
    float* C;
    int vt = 0;
    switch (z) {
        case 0: W = Wqa; C = g_qa; break;
        case 1: W = Wka; C = g_ka; break;
        case 2: W = Wva;
#if HAS_TCGEN05
            C = g_vaT; vt = 1;
#else
            C = g_va;
#endif
            break;
        case 3: W = Wqb; C = g_qb; break;
        case 4: W = Wkb; C = g_kb; break;
        default: W = Wvb;
#if HAS_TCGEN05
            C = g_vbT; vt = 1;
#else
            C = g_vb;
#endif
            break;
    }
    gemm_impl(A, W, C, vt);
}

__global__ __launch_bounds__(256) void oproj_gemm(
    const float* __restrict__ Woa, const float* __restrict__ Wob)
{
    const int z = blockIdx.z;
    const float* A = z ? g_ob : g_oa;
    const float* W = z ? Wob  : Woa;
    float*       C = z ? g_pb : g_pa;
    gemm_impl(A, W, C, 0);
}

// ---------------------------------------------------------------------------
// tcgen05 flash cross-attention, pipelined (R6/R10-validated, 128-key tiles).
// grid (16 q-tiles, 32 bh, 2 branches), 256 threads.
// TMEM: S0 cols [0,128), S1 [128,256), O [256,320).
// ---------------------------------------------------------------------------
#define A_MB1  8
#define A_MB2  16
#define A_LS   32
#define A_Q    2048
#define A_K0   (A_Q + 32768)
#define A_V0   (A_Q + 3 * 32768)
#define ATT_SMEM (A_Q + 6 * 32768)   // 198656

#define IDESC_ATT1 ((1u<<4)|(2u<<7)|(2u<<10)|(16u<<17)|(8u<<24))  // N=128, M=128
#define IDESC_ATT2 ((1u<<4)|(2u<<7)|(2u<<10)|(8u<<17)|(8u<<24))   // N=64,  M=128

#if HAS_TCGEN05
// [128 rows x 64 floats] K-major blocked atoms (16 atom-rows x 2 atom-cols)
__device__ __forceinline__ void att_load_qk(uint32_t base, const float* src,
                                            int row0, int col0, int t)
{
#pragma unroll
    for (int i = 0; i < 8; i++) {
        const int chunk = t + i * 256;
        const int r = chunk >> 4;
        const int c = (chunk & 15) * 4;
        const uint32_t off = (uint32_t)(((r >> 3) + (c >> 5) * 16) * 1024
                           + (r & 7) * 128 + (c & 31) * 4);
        cp16(base + SWZ(off), src + (size_t)(row0 + r) * HALFD + col0 + c);
    }
}
// [64 rows x 128 floats] K-major blocked atoms (8 atom-rows x 4 atom-cols)
__device__ __forceinline__ void att_load_vt(uint32_t base, const float* srcT,
                                            int kt, int t)
{
#pragma unroll
    for (int i = 0; i < 8; i++) {
        const int chunk = t + i * 256;
        const int r = chunk >> 5;
        const int c = (chunk & 31) * 4;
        const uint32_t off = (uint32_t)(((r >> 3) + (c >> 5) * 8) * 1024
                           + (r & 7) * 128 + (c & 31) * 4);
        cp16(base + SWZ(off), srcT + (size_t)r * LEN + kt * 128 + c);
    }
}

__device__ __forceinline__ void att_gemm1(uint32_t sm, uint32_t s_t, int kbuf)
{
    const uint64_t ad = mk_desc(sm + A_Q);
    const uint64_t bd = mk_desc(sm + A_K0 + kbuf * 32768);
#pragma unroll
    for (int kc = 0; kc < 8; kc++) {
        const uint32_t u = (kc >> 2) * 1024 + (kc & 3) * 2;
        mma_tf32_ss(s_t, ad + u, bd + u, IDESC_ATT1, kc > 0);
    }
    tc_commit(sm + A_MB1);
}
#endif

__global__ __launch_bounds__(256) void attn_kernel()
{
#if HAS_TCGEN05
    extern __shared__ char smem[];
    const uint32_t sm = smem_u32(smem);
    const int t = threadIdx.x;
    const int w = t >> 5;
    const int lane = t & 31;
    const int branch = blockIdx.z;
    const int bh = blockIdx.y;
    const int b = bh >> 4, h = bh & 15;
    const int tq = blockIdx.x;

    const float* __restrict__ Q  = branch ? g_qb  : g_qa;
    const float* __restrict__ K  = branch ? g_ka  : g_kb;
    const float* __restrict__ VT = branch ? g_vaT : g_vbT;
    float* __restrict__ O        = branch ? g_ob  : g_oa;
    const float* vt_slice = VT + (size_t)bh * HD * LEN;

    if (w == 0) {
        asm volatile("tcgen05.alloc.cta_group::1.sync.aligned.shared::cta.b32 [%0], %1;"
                     :: "r"(sm + 0), "r"(512u) : "memory");
    }
    if (t == 0) { mbar_init(sm + A_MB1, 1); mbar_init(sm + A_MB2, 1); }
    __syncthreads();
    uint32_t tmem;
    asm volatile("ld.shared.b32 %0, [%1];" : "=r"(tmem) : "r"(sm + 0));
    const uint32_t O_t = tmem + 256;

    const int qrow0 = b * LEN + tq * 128;
    const int krow0 = b * LEN;
    const uint32_t warp_off = (uint32_t)(w & 3) << 21;

    att_load_qk(sm + A_Q,  Q, qrow0, h * HD, t);
    att_load_qk(sm + A_K0, K, krow0, h * HD, t);
    att_load_vt(sm + A_V0, vt_slice, 0, t);
    cp_commit();
    att_load_qk(sm + A_K0 + 32768, K, krow0 + 128, h * HD, t);
    att_load_vt(sm + A_V0 + 32768, vt_slice, 1, t);
    cp_commit();

    cp_wait1();
    __syncthreads();
    if (w == 0) {
        asm volatile("fence.proxy.async.shared::cta;" ::: "memory");
        if (elect1()) att_gemm1(sm, tmem + 0, 0);      // GEMM1(0) -> S0
    }

    // p = exp(s/sqrt(128)) = exp2(s * log2e/sqrt(128))
    const float c_exp2 = 0.12751743f;   // 1.4426950408889634 / sqrt(128)
    float lsum = 0.f;
    const int cb = (w >> 2) * 64;   // this warp's score-column half

    for (int kt = 0; kt < 16; kt++) {
        const uint32_t S_t = tmem + (kt & 1) * 128;

        mbar_wait(sm + A_MB1, kt & 1);
        asm volatile("tcgen05.fence::after_thread_sync;" ::: "memory");

        if (kt + 1 < 16) {
            cp_wait0();
            if (kt >= 1) mbar_wait(sm + A_MB2, (kt - 1) & 1);
            __syncthreads();
            if (w == 0) {
                asm volatile("fence.proxy.async.shared::cta;" ::: "memory");
                if (elect1())
                    att_gemm1(sm, tmem + ((kt + 1) & 1) * 128, (kt + 1) & 1);
            }
            if (kt + 2 < 16) {
                att_load_qk(sm + A_K0 + (kt & 1) * 32768, K,
                            krow0 + (kt + 2) * 128, h * HD, t);
                att_load_vt(sm + A_V0 + ((kt + 2) % 3) * 32768, vt_slice, kt + 2, t);
                cp_commit();
            }
        }

        {
            uint32_t r0[32], r1[32];
            LDTM_X32(r0, S_t + cb + warp_off);
            LDTM_X32(r1, S_t + cb + 32 + warp_off);
            asm volatile("tcgen05.wait::ld.sync.aligned;" ::: "memory");
            float part = 0.f;
#pragma unroll
            for (int j = 0; j < 32; j++) {
                float p = exp2f(__uint_as_float(r0[j]) * c_exp2);
                part += p;
                r0[j] = __float_as_uint(p);
            }
#pragma unroll
            for (int j = 0; j < 32; j++) {
                float p = exp2f(__uint_as_float(r1[j]) * c_exp2);
                part += p;
                r1[j] = __float_as_uint(p);
            }
            lsum += part;
            STTM_X32(S_t + cb + warp_off, r0);
            STTM_X32(S_t + cb + 32 + warp_off, r1);
            asm volatile("tcgen05.wait::st.sync.aligned;" ::: "memory");
            asm volatile("tcgen05.fence::before_thread_sync;" ::: "memory");
        }
        __syncthreads();

        if (w == 0) {
            if (elect1()) {
                asm volatile("tcgen05.fence::after_thread_sync;" ::: "memory");
                const uint64_t bd = mk_desc(sm + A_V0 + (kt % 3) * 32768);
#pragma unroll
                for (int kc = 0; kc < 16; kc++) {
                    const uint64_t u = (kc >> 2) * 512 + (kc & 3) * 2;
                    mma_tf32_ts(O_t, S_t + kc * 8, bd + u, IDESC_ATT2,
                                (kt > 0) || (kc > 0));
                }
                tc_commit(sm + A_MB2);
            }
        }
    }

    float* ls = (float*)(smem + A_LS);
    const int r = (w & 3) * 32 + lane;
    ls[(w >> 2) * 128 + r] = lsum;
    __syncthreads();
    const float inv_l = 1.f / (ls[r] + ls[128 + r]);

    mbar_wait(sm + A_MB2, 1);
    asm volatile("tcgen05.fence::after_thread_sync;" ::: "memory");

    {
        const int c0 = (w >> 2) * 32;
        uint32_t rr[32];
        LDTM_X32(rr, O_t + c0 + warp_off);
        asm volatile("tcgen05.wait::ld.sync.aligned;" ::: "memory");
        float* op = O + (size_t)(qrow0 + r) * HALFD + h * HD + c0;
#pragma unroll
        for (int j = 0; j < 8; j++) {
            float4 v;
            v.x = __uint_as_float(rr[4*j])   * inv_l;
            v.y = __uint_as_float(rr[4*j+1]) * inv_l;
            v.z = __uint_as_float(rr[4*j+2]) * inv_l;
            v.w = __uint_as_float(rr[4*j+3]) * inv_l;
            *(float4*)(op + 4 * j) = v;
        }
    }

    __syncthreads();
    if (t == 0) {
        asm volatile("mbarrier.inval.shared.b64 [%0];" :: "r"(sm + A_MB1) : "memory");
        asm volatile("mbarrier.inval.shared.b64 [%0];" :: "r"(sm + A_MB2) : "memory");
    }
    __syncthreads();
    if (w == 0) {
        asm volatile("tcgen05.relinquish_alloc_permit.cta_group::1.sync.aligned;");
        asm volatile("tcgen05.dealloc.cta_group::1.sync.aligned.b32 %0, %1;"
                     :: "r"(tmem), "r"(512u));
    }
#else
    // ---------------- SIMT f32x2 fallback (reads untransposed V) ----------
    const int branch = blockIdx.z;
    const float* __restrict__ Q = branch ? g_qb : g_qa;
    const float* __restrict__ K = branch ? g_ka : g_kb;
    const float* __restrict__ V = branch ? g_va : g_vb;
    float* __restrict__ O       = branch ? g_ob : g_oa;

    const int bh = blockIdx.y;
    const int b  = bh >> 4;
    const int h  = bh & 15;
    const size_t base = (size_t)b * LEN * HALFD + (size_t)h * HD;

    const int t    = threadIdx.x;
    const int qi   = t >> 1;
    const int half = t & 1;
    const int l    = blockIdx.x * 128 + qi;

    __shared__ __align__(16) float Ks[64][68];
    __shared__ __align__(16) float Vs[64][68];

    const float* qp = Q + base + (size_t)l * HALFD + 4 * half;
    uint64_t q2[16];
    {
        const uint64_t* qd = (const uint64_t*)qp;
#pragma unroll
        for (int j = 0; j < 8; j++) {
            q2[2*j]   = qd[4*j];
            q2[2*j+1] = qd[4*j + 1];
        }
    }

    uint64_t acc2[16];
#pragma unroll
    for (int j = 0; j < 16; j++) acc2[j] = 0ull;
    float mval = -1e30f, lsum = 0.f;
    const float inv_scale = 0.08838834764831845f;

    const int lr = t >> 2;
    const int lc = (t & 3) * 16;

    for (int kt = 0; kt < LEN; kt += 64) {
        __syncthreads();
        {
            const float* kp = K + base + (size_t)(kt + lr) * HALFD + lc;
            const float* vp = V + base + (size_t)(kt + lr) * HALFD + lc;
#pragma unroll
            for (int j = 0; j < 4; j++) {
                *(float4*)&Ks[lr][lc + 4 * j] = *(const float4*)(kp + 4 * j);
                *(float4*)&Vs[lr][lc + 4 * j] = *(const float4*)(vp + 4 * j);
            }
        }
        __syncthreads();

#pragma unroll 2
        for (int k = 0; k < 64; k++) {
            const uint64_t* krow = (const uint64_t*)(&Ks[k][4 * half]);
            uint64_t s2 = 0ull;
#pragma unroll
            for (int j = 0; j < 8; j++) {
                s2 = fma2(q2[2*j],   krow[4*j],     s2);
                s2 = fma2(q2[2*j+1], krow[4*j + 1], s2);
            }
            float slo, shi;
            upk2(s2, slo, shi);
            float s = slo + shi;
            s += __shfl_xor_sync(0xffffffffu, s, 1);
            s *= inv_scale;

            float p;
            if (s > mval) {
                const float cfac = __expf(mval - s);
                mval = s;
                lsum *= cfac;
                const uint64_t c2 = pk2(cfac, cfac);
#pragma unroll
                for (int j = 0; j < 16; j++) acc2[j] = mul2(acc2[j], c2);
                p = 1.f;
            } else {
                p = __expf(s - mval);
            }
            lsum += p;

            const uint64_t p2 = pk2(p, p);
            const uint64_t* vrow = (const uint64_t*)(&Vs[k][4 * half]);
#pragma unroll
            for (int j = 0; j < 8; j++) {
                acc2[2*j]   = fma2(p2, vrow[4*j],     acc2[2*j]);
                acc2[2*j+1] = fma2(p2, vrow[4*j + 1], acc2[2*j+1]);
            }
        }
    }

    const float inv_l = 1.f / lsum;
    const uint64_t inv2 = pk2(inv_l, inv_l);
    uint64_t* od = (uint64_t*)(O + base + (size_t)l * HALFD + 4 * half);
#pragma unroll
    for (int j = 0; j < 8; j++) {
        od[4*j]     = mul2(acc2[2*j],   inv2);
        od[4*j + 1] = mul2(acc2[2*j+1], inv2);
    }
#endif
}

// ---------------------------------------------------------------------------
// Residual + LayerNorm.
// ---------------------------------------------------------------------------
__global__ __launch_bounds__(256) void ln_kernel(
    const float* __restrict__ xa, const float* __restrict__ xb,
    const float* __restrict__ ga, const float* __restrict__ ba,
    const float* __restrict__ gb, const float* __restrict__ bb,
    float* __restrict__ out)
{
    const int row   = blockIdx.x;
    const int which = blockIdx.y;
    const float* x     = which ? xb   : xa;
    const float* p     = which ? g_pb : g_pa;
    const float* gamma = which ? gb   : ga;
    const float* beta  = which ? bb   : ba;
    float* o = out + (size_t)which * ELEMS + (size_t)row * HALFD;

    const int t = threadIdx.x;
    float4 xv = ((const float4*)(x + (size_t)row * HALFD))[t];
    float4 pv = ((const float4*)(p + (size_t)row * HALFD))[t];
    float4 sv = make_float4(xv.x + pv.x, xv.y + pv.y, xv.z + pv.z, xv.w + pv.w);

    float s  = sv.x + sv.y + sv.z + sv.w;
    float sq = sv.x * sv.x + sv.y * sv.y + sv.z * sv.z + sv.w * sv.w;
#pragma unroll
    for (int off = 16; off > 0; off >>= 1) {
        s  += __shfl_xor_sync(0xffffffffu, s,  off);
        sq += __shfl_xor_sync(0xffffffffu, sq, off);
    }
    __shared__ float ss[8], ssq[8];
    if ((t & 31) == 0) { ss[t >> 5] = s; ssq[t >> 5] = sq; }
    __syncthreads();
    float tot = 0.f, totq = 0.f;
#pragma unroll
    for (int i = 0; i < 8; i++) { tot += ss[i]; totq += ssq[i]; }

    const float mean = tot * (1.f / HALFD);
    const float var  = totq * (1.f / HALFD) - mean * mean;
    const float rstd = rsqrtf(var + 1e-5f);

    float4 g4 = ((const float4*)gamma)[t];
    float4 b4 = ((const float4*)beta)[t];
    float4 rr;
    rr.x = (sv.x - mean) * rstd * g4.x + b4.x;
    rr.y = (sv.y - mean) * rstd * g4.y + b4.y;
    rr.z = (sv.z - mean) * rstd * g4.z + b4.z;
    rr.w = (sv.w - mean) * rstd * g4.w + b4.w;
    ((float4*)o)[t] = rr;
}

// ---------------------------------------------------------------------------
extern "C" void kernel_launch(void* const* d_in, const int* in_sizes, int n_in,
                              void* d_out, int out_size)
{
    const float* x_a  = (const float*)d_in[0];
    const float* x_b  = (const float*)d_in[1];
    const float* Wq_a = (const float*)d_in[2];
    const float* Wq_b = (const float*)d_in[3];
    const float* Wk_a = (const float*)d_in[4];
    const float* Wk_b = (const float*)d_in[5];
    const float* Wv_a = (const float*)d_in[6];
    const float* Wv_b = (const float*)d_in[7];
    const float* Wo_a = (const float*)d_in[8];
    const float* Wo_b = (const float*)d_in[9];
    const float* ga   = (const float*)d_in[10];
    const float* ba   = (const float*)d_in[11];
    const float* gb   = (const float*)d_in[12];
    const float* bb   = (const float*)d_in[13];
    float* out = (float*)d_out;

    cudaFuncSetAttribute(qkv_gemm, cudaFuncAttributeMaxDynamicSharedMemorySize,
                         SMEM_GEMM_TOTAL);
    cudaFuncSetAttribute(oproj_gemm, cudaFuncAttributeMaxDynamicSharedMemorySize,
                         SMEM_GEMM_TOTAL);
    cudaFuncSetAttribute(attn_kernel, cudaFuncAttributeMaxDynamicSharedMemorySize,
                         ATT_SMEM);

    dim3 gq(HALFD / GTN, MROWS / GTM, 6);   // (4, 16, 6)
    qkv_gemm<<<gq, 256, SMEM_GEMM_TOTAL>>>(x_a, x_b, Wq_a, Wk_a, Wv_a,
                                           Wq_b, Wk_b, Wv_b);

    // (v_transpose launch removed: tcgen05 qkv writes the transposed layout
    //  directly, and the SIMT fallback attention reads untransposed V.)

    dim3 gat(LEN / 128, BN * NH, 2);
    attn_kernel<<<gat, 256, ATT_SMEM>>>();

    dim3 go(HALFD / GTN, MROWS / GTM, 2);   // (4, 16, 2)
    oproj_gemm<<<go, 256, SMEM_GEMM_TOTAL>>>(Wo_a, Wo_b);

    dim3 gl(MROWS, 2);
    ln_kernel<<<gl, 256>>>(x_a, x_b, ga, ba, gb, bb, out);
}

// round 13
// speedup vs baseline: 2.0364x; 1.1057x over previous
#include <cuda_runtime.h>
#include <cstdint>
#include <math.h>

// Problem constants
#define BN    2
#define LEN   2048
#define HALFD 1024
#define NH    16
#define HD    64
#define MROWS (BN * LEN)        // 4096
#define ELEMS (MROWS * HALFD)   // 4194304 per tensor

// Scratch (device globals: no allocation allowed)
__device__ float g_qa[ELEMS];
__device__ float g_ka[ELEMS];
__device__ float g_va[ELEMS];
__device__ float g_qb[ELEMS];
__device__ float g_kb[ELEMS];
__device__ float g_vb[ELEMS];
__device__ float g_oa[ELEMS];
__device__ float g_ob[ELEMS];
__device__ float g_pa[ELEMS];
__device__ float g_pb[ELEMS];
__device__ float g_vaT[ELEMS];   // [bh][64][2048] transposed V, branch a
__device__ float g_vbT[ELEMS];   // [bh][64][2048] transposed V, branch b

#if defined(__CUDA_ARCH__) && (defined(__CUDA_ARCH_FEAT_SM103_ALL) || \
    defined(__CUDA_ARCH_FEAT_SM100_ALL) || defined(__CUDA_ARCH_FEAT_SM101_ALL))
#define HAS_TCGEN05 1
#else
#define HAS_TCGEN05 0
#endif

// ---------------------------------------------------------------------------
// packed f32x2 helpers (legal in plain pass)
// ---------------------------------------------------------------------------
__device__ __forceinline__ uint64_t pk2(float lo, float hi) {
    uint64_t r;
    asm("mov.b64 %0, {%1, %2};" : "=l"(r) : "f"(lo), "f"(hi));
    return r;
}
__device__ __forceinline__ void upk2(uint64_t v, float& lo, float& hi) {
    asm("mov.b64 {%0, %1}, %2;" : "=f"(lo), "=f"(hi) : "l"(v));
}
__device__ __forceinline__ uint64_t fma2(uint64_t a, uint64_t b, uint64_t c) {
    uint64_t d;
    asm("fma.rn.f32x2 %0, %1, %2, %3;" : "=l"(d) : "l"(a), "l"(b), "l"(c));
    return d;
}
__device__ __forceinline__ uint64_t mul2(uint64_t a, uint64_t b) {
    uint64_t d;
    asm("mul.rn.f32x2 %0, %1, %2;" : "=l"(d) : "l"(a), "l"(b));
    return d;
}

// ---------------------------------------------------------------------------
// common asm helpers
// ---------------------------------------------------------------------------
#define SWZ(off) ((off) ^ (((off) >> 3) & 0x70))

__device__ __forceinline__ uint32_t smem_u32(const void* p) {
    uint32_t a;
    asm("{ .reg .u64 t; cvta.to.shared.u64 t, %1; cvt.u32.u64 %0, t; }"
        : "=r"(a) : "l"(p));
    return a;
}
__device__ __forceinline__ void cp16(uint32_t dst, const void* src) {
    asm volatile("cp.async.cg.shared.global [%0], [%1], 16;" :: "r"(dst), "l"(src));
}
__device__ __forceinline__ void cp_commit() {
    asm volatile("cp.async.commit_group;" ::: "memory");
}
__device__ __forceinline__ void cp_wait1() {
    asm volatile("cp.async.wait_group 1;" ::: "memory");
}
__device__ __forceinline__ void cp_wait0() {
    asm volatile("cp.async.wait_group 0;" ::: "memory");
}

#if HAS_TCGEN05
__device__ __forceinline__ uint32_t elect1() {
    uint32_t p;
    asm volatile("{ .reg .pred p; elect.sync _|p, 0xFFFFFFFF; selp.b32 %0,1,0,p; }"
                 : "=r"(p));
    return p;
}
__device__ __forceinline__ void mbar_init(uint32_t a, uint32_t cnt) {
    asm volatile("mbarrier.init.shared.b64 [%0], %1;" :: "r"(a), "r"(cnt) : "memory");
}
__device__ __forceinline__ void mbar_wait(uint32_t a, uint32_t par) {
    asm volatile(
        "{\n\t.reg .pred P;\n"
        "W_%=:\n\t"
        "mbarrier.try_wait.parity.acquire.cta.shared::cta.b64 P, [%0], %1, 0x989680;\n\t"
        "@!P bra W_%=;\n\t}"
        :: "r"(a), "r"(par) : "memory");
}
__device__ __forceinline__ void tc_commit(uint32_t mbar) {
    asm volatile(
        "tcgen05.commit.cta_group::1.mbarrier::arrive::one.shared::cluster.b64 [%0];"
        :: "r"(mbar) : "memory");
}
__device__ __forceinline__ uint64_t mk_desc(uint32_t addr) {
    const uint64_t base = (uint64_t(2) << 61) | (uint64_t(1) << 46)
                        | (uint64_t(64) << 32) | (uint64_t(1) << 16);
    return base | ((uint64_t)(addr >> 4) & 0x3FFF);
}
__device__ __forceinline__ void mma_tf32_ss(uint32_t d, uint64_t ad, uint64_t bd,
                                            uint32_t idesc, uint32_t en) {
    asm volatile(
        "{\n\t.reg .pred p;\n\t"
        "setp.ne.u32 p, %4, 0;\n\t"
        "tcgen05.mma.cta_group::1.kind::tf32 [%0], %1, %2, %3, {%5,%5,%5,%5}, p;\n\t}"
        :: "r"(d), "l"(ad), "l"(bd), "r"(idesc), "r"(en), "r"(0u)
        : "memory");
}
__device__ __forceinline__ void mma_tf32_ts(uint32_t d, uint32_t a, uint64_t bd,
                                            uint32_t idesc, uint32_t en) {
    asm volatile(
        "{\n\t.reg .pred p;\n\t"
        "setp.ne.u32 p, %4, 0;\n\t"
        "tcgen05.mma.cta_group::1.kind::tf32 [%0], [%1], %2, %3, {%5,%5,%5,%5}, p;\n\t}"
        :: "r"(d), "r"(a), "l"(bd), "r"(idesc), "r"(en), "r"(0u)
        : "memory");
}

#define LDTM_X32(r, addr) \
    asm volatile( \
        "tcgen05.ld.sync.aligned.32x32b.x32.b32 " \
        "{%0,%1,%2,%3,%4,%5,%6,%7,%8,%9,%10,%11,%12,%13,%14,%15," \
        "%16,%17,%18,%19,%20,%21,%22,%23,%24,%25,%26,%27,%28,%29,%30,%31}, [%32];" \
        : "=r"((r)[0]), "=r"((r)[1]), "=r"((r)[2]), "=r"((r)[3]), \
          "=r"((r)[4]), "=r"((r)[5]), "=r"((r)[6]), "=r"((r)[7]), \
          "=r"((r)[8]), "=r"((r)[9]), "=r"((r)[10]), "=r"((r)[11]), \
          "=r"((r)[12]), "=r"((r)[13]), "=r"((r)[14]), "=r"((r)[15]), \
          "=r"((r)[16]), "=r"((r)[17]), "=r"((r)[18]), "=r"((r)[19]), \
          "=r"((r)[20]), "=r"((r)[21]), "=r"((r)[22]), "=r"((r)[23]), \
          "=r"((r)[24]), "=r"((r)[25]), "=r"((r)[26]), "=r"((r)[27]), \
          "=r"((r)[28]), "=r"((r)[29]), "=r"((r)[30]), "=r"((r)[31]) \
        : "r"(addr))

#define STTM_X32(addr, r) \
    asm volatile( \
        "tcgen05.st.sync.aligned.32x32b.x32.b32 [%0], " \
        "{%1,%2,%3,%4,%5,%6,%7,%8,%9,%10,%11,%12,%13,%14,%15,%16," \
        "%17,%18,%19,%20,%21,%22,%23,%24,%25,%26,%27,%28,%29,%30,%31,%32};" \
        :: "r"(addr), \
           "r"((r)[0]), "r"((r)[1]), "r"((r)[2]), "r"((r)[3]), \
           "r"((r)[4]), "r"((r)[5]), "r"((r)[6]), "r"((r)[7]), \
           "r"((r)[8]), "r"((r)[9]), "r"((r)[10]), "r"((r)[11]), \
           "r"((r)[12]), "r"((r)[13]), "r"((r)[14]), "r"((r)[15]), \
           "r"((r)[16]), "r"((r)[17]), "r"((r)[18]), "r"((r)[19]), \
           "r"((r)[20]), "r"((r)[21]), "r"((r)[22]), "r"((r)[23]), \
           "r"((r)[24]), "r"((r)[25]), "r"((r)[26]), "r"((r)[27]), \
           "r"((r)[28]), "r"((r)[29]), "r"((r)[30]), "r"((r)[31]) \
        : "memory")
#endif  // HAS_TCGEN05

// ---------------------------------------------------------------------------
// Projection GEMM: C[m,n] = sum_k A[m,k]*W[n,k].
// Tile 256x256 (two M=128 MMA chains -> TMEM D0 cols 0-255, D1 256-511),
// K staged 32 floats, 3 buffers. Pipeline shifted one stage: at iteration s
// we wait MMA(s-1) (issued a full period ago -> ~free) and load stage s+2,
// so the tensor queue always holds the current stage instead of being
// drained every iteration.
// vt=1 epilogue writes V directly in [bh][d][tok] transposed layout.
// ---------------------------------------------------------------------------
#define GTM 256
#define GTN 256
#define KSTEP 32
#define NSTAGES (HALFD / KSTEP)     // 32
#define G_NBUF 3
#define G_ABYTES  32768             // 256 rows x 128B
#define G_BUFSTRIDE 65536
#define SM_MBAR  8
#define SM_TILES 1024
#define SMEM_GEMM_TOTAL (SM_TILES + G_NBUF * G_BUFSTRIDE)   // 197632

// per-MMA idesc: M=128, N=256, tf32
#define IDESC_G ((1u<<4)|(2u<<7)|(2u<<10)|((GTN/8)<<17)|(8u<<24))

__device__ __forceinline__ void g_load_stage(uint32_t sm_base,
                                             const float* __restrict__ A,
                                             const float* __restrict__ W,
                                             int bm, int bn, int s, int buf, int t)
{
    const int k0  = s * KSTEP;
    const int rb  = t >> 3;        // 0..31
    const int c16 = (t & 7);       // 16B chunk within 128B row
    const uint32_t abase = sm_base + SM_TILES + buf * G_BUFSTRIDE;
    const uint32_t bbase = abase + G_ABYTES;
#pragma unroll
    for (int i = 0; i < 8; i++) {
        const int row = i * 32 + rb;
        const uint32_t off = row * 128 + c16 * 16;
        cp16(abase + SWZ(off), A + (size_t)(bm + row) * HALFD + k0 + c16 * 4);
    }
#pragma unroll
    for (int i = 0; i < 8; i++) {
        const int row = i * 32 + rb;
        const uint32_t off = row * 128 + c16 * 16;
        cp16(bbase + SWZ(off), W + (size_t)(bn + row) * HALFD + k0 + c16 * 4);
    }
}

#if !HAS_TCGEN05
// SIMT f32x2 128x128 sub-tile (fallback only)
__device__ void gemm128_fb(const float* __restrict__ A,
                           const float* __restrict__ W,
                           float* __restrict__ C, int bm, int bn)
{
    __shared__ float As[16][128];
    __shared__ float Bs[16][128];
    const int t  = threadIdx.x;
    const int tm = (t >> 4) * 8;
    const int tn = (t & 15) * 8;

    uint64_t acc2[8][4];
#pragma unroll
    for (int i = 0; i < 8; i++)
#pragma unroll
        for (int j = 0; j < 4; j++) acc2[i][j] = 0ull;

    const int lrow = t >> 2;
    const int lkc  = (t & 3) * 4;
    const int swz  = (t & 3) * 8;

    for (int k0 = 0; k0 < 1024; k0 += 16) {
#pragma unroll
        for (int i = 0; i < 2; i++) {
            const int row = lrow + i * 64;
            float4 a = *(const float4*)(A + (size_t)(bm + row) * 1024 + k0 + lkc);
            float4 b = *(const float4*)(W + (size_t)(bn + row) * 1024 + k0 + lkc);
            const int sc = row ^ swz;
            As[lkc + 0][sc] = a.x; As[lkc + 1][sc] = a.y;
            As[lkc + 2][sc] = a.z; As[lkc + 3][sc] = a.w;
            Bs[lkc + 0][sc] = b.x; Bs[lkc + 1][sc] = b.y;
            Bs[lkc + 2][sc] = b.z; Bs[lkc + 3][sc] = b.w;
        }
        __syncthreads();
#pragma unroll
        for (int kk = 0; kk < 16; kk++) {
            const int sa = (kk >> 2) * 8;
            const int ca = tm ^ sa;
            const int cb = tn ^ sa;
            float a8[8];
            *(float4*)&a8[0] = *(const float4*)&As[kk][ca];
            *(float4*)&a8[4] = *(const float4*)&As[kk][ca + 4];
            float4 b0 = *(const float4*)&Bs[kk][cb];
            float4 b1 = *(const float4*)&Bs[kk][cb + 4];
            uint64_t b2[4];
            b2[0] = pk2(b0.x, b0.y); b2[1] = pk2(b0.z, b0.w);
            b2[2] = pk2(b1.x, b1.y); b2[3] = pk2(b1.z, b1.w);
#pragma unroll
            for (int i = 0; i < 8; i++) {
                const uint64_t ai = pk2(a8[i], a8[i]);
#pragma unroll
                for (int j = 0; j < 4; j++)
                    acc2[i][j] = fma2(ai, b2[j], acc2[i][j]);
            }
        }
        __syncthreads();
    }
#pragma unroll
    for (int i = 0; i < 8; i++) {
        float c[8];
#pragma unroll
        for (int j = 0; j < 4; j++) upk2(acc2[i][j], c[2*j], c[2*j+1]);
        float* cp = C + (size_t)(bm + tm + i) * 1024 + bn + tn;
        *(float4*)(cp)     = make_float4(c[0], c[1], c[2], c[3]);
        *(float4*)(cp + 4) = make_float4(c[4], c[5], c[6], c[7]);
    }
}
#endif

__device__ void gemm_impl(const float* __restrict__ A,
                          const float* __restrict__ W,
                          float* __restrict__ C, int vt)
{
#if HAS_TCGEN05
    extern __shared__ char smem[];
    const uint32_t sm_base = smem_u32(smem);
    const int t   = threadIdx.x;
    const int wid = t >> 5;
    const int lid = t & 31;
    const int bm  = blockIdx.y * GTM;
    const int bn  = blockIdx.x * GTN;

    if (wid == 0) {
        asm volatile("tcgen05.alloc.cta_group::1.sync.aligned.shared::cta.b32 [%0], %1;"
                     :: "r"(sm_base + 0), "r"(512u) : "memory");
    }
    if (t == 0) {
        mbar_init(sm_base + SM_MBAR + 0, 1);
        mbar_init(sm_base + SM_MBAR + 8, 1);
        mbar_init(sm_base + SM_MBAR + 16, 1);
    }
    __syncthreads();
    uint32_t tmem;
    asm volatile("ld.shared.b32 %0, [%1];" : "=r"(tmem) : "r"(sm_base + 0));

    // prologue: stages 0,1 (buffers 0,1); stage 2 loaded at iteration 0.
    g_load_stage(sm_base, A, W, bm, bn, 0, 0, t); cp_commit();
    g_load_stage(sm_base, A, W, bm, bn, 1, 1, t); cp_commit();

    for (int s = 0; s < NSTAGES; s++) {
        const int buf = s % 3;
        if (s == NSTAGES - 1) cp_wait0(); else cp_wait1();
        __syncthreads();

        if (wid == 0) {
            asm volatile("fence.proxy.async.shared::cta;" ::: "memory");
            if (elect1()) {
                const uint32_t ab = sm_base + SM_TILES + buf * G_BUFSTRIDE;
                const uint64_t ad0 = mk_desc(ab);
                const uint64_t ad1 = mk_desc(ab + 16384);
                const uint64_t bd  = mk_desc(ab + G_ABYTES);
#pragma unroll
                for (int c = 0; c < 4; c++) {
                    const uint32_t en = (s > 0) || (c > 0);
                    mma_tf32_ss(tmem,       ad0 + 2 * c, bd + 2 * c, IDESC_G, en);
                    mma_tf32_ss(tmem + 256, ad1 + 2 * c, bd + 2 * c, IDESC_G, en);
                }
                tc_commit(sm_base + SM_MBAR + 8 * buf);
            }
        }

        if (s + 2 < NSTAGES) {
            // load(s+2) overwrites buf (s+2)%3, which held stage s-1:
            // wait MMA(s-1) (issued a full period ago -> usually complete).
            if (s >= 1)
                mbar_wait(sm_base + SM_MBAR + 8 * ((s - 1) % 3),
                          (uint32_t)(((s - 1) / 3) & 1));
            g_load_stage(sm_base, A, W, bm, bn, s + 2, (s + 2) % 3, t);
            cp_commit();
        }
    }

    // stage 31 committed to mbar[1] as commit #11 there -> phase 10, parity 0.
    // (threads last observed mbar[1] at s=29 waiting phase 9 -> adjacent.)
    mbar_wait(sm_base + SM_MBAR + 8 * ((NSTAGES - 1) % 3),
              (uint32_t)(((NSTAGES - 1) / 3) & 1));
    asm volatile("tcgen05.fence::after_thread_sync;" ::: "memory");

    {
        const int dtile = wid >> 2;
        const int row = bm + dtile * 128 + (wid & 3) * 32 + lid;
        if (!vt) {
#pragma unroll
            for (int cc = 0; cc < 8; cc++) {
                uint32_t r[32];
                LDTM_X32(r, tmem + dtile * 256 + cc * 32);
                asm volatile("tcgen05.wait::ld.sync.aligned;" ::: "memory");
                float* cp = C + (size_t)row * HALFD + bn + cc * 32;
#pragma unroll
                for (int j = 0; j < 8; j++)
                    *(uint4*)(cp + 4 * j) = make_uint4(r[4*j], r[4*j+1], r[4*j+2], r[4*j+3]);
            }
        } else {
            // transposed V write: dst[(b*1024 + f) * 2048 + tok],
            // f = bn + cc*32 + j, tok = row & 2047, b = row >> 11.
            const int tok = row & (LEN - 1);
            const int bidx = row >> 11;
            float* dstb = C + (size_t)bidx * 1024 * LEN + tok;
#pragma unroll
            for (int cc = 0; cc < 8; cc++) {
                uint32_t r[32];
                LDTM_X32(r, tmem + dtile * 256 + cc * 32);
                asm volatile("tcgen05.wait::ld.sync.aligned;" ::: "memory");
                const int f0 = bn + cc * 32;
#pragma unroll
                for (int j = 0; j < 32; j++)
                    dstb[(size_t)(f0 + j) * LEN] = __uint_as_float(r[j]);
            }
        }
    }

    __syncthreads();
    if (t == 0) {
        asm volatile("mbarrier.inval.shared.b64 [%0];" :: "r"(sm_base + SM_MBAR + 0) : "memory");
        asm volatile("mbarrier.inval.shared.b64 [%0];" :: "r"(sm_base + SM_MBAR + 8) : "memory");
        asm volatile("mbarrier.inval.shared.b64 [%0];" :: "r"(sm_base + SM_MBAR + 16) : "memory");
    }
    __syncthreads();
    if (wid == 0) {
        asm volatile("tcgen05.relinquish_alloc_permit.cta_group::1.sync.aligned;");
        asm volatile("tcgen05.dealloc.cta_group::1.sync.aligned.b32 %0, %1;"
                     :: "r"(tmem), "r"(512u));
    }
#else
    (void)vt;
    const int bm = blockIdx.y * GTM;
    const int bn = blockIdx.x * GTN;
#pragma unroll
    for (int ii = 0; ii < 2; ii++)
#pragma unroll
        for (int jj = 0; jj < 2; jj++)
            gemm128_fb(A, W, C, bm + ii * 128, bn + jj * 128);
#endif
}

__global__ __launch_bounds__(256) void qkv_gemm(
    const float* __restrict__ xa, const float* __restrict__ xb,
    const float* __restrict__ Wqa, const float* __restrict__ Wka, const float* __restrict__ Wva,
    const float* __restrict__ Wqb, const float* __restrict__ Wkb, const float* __restrict__ Wvb)
{
    const int z = blockIdx.z;
    const float* A = (z < 3) ? xa : xb;
    const float* W;
    float* C;
    int vt = 0;
    switch (z) {
        case 0: W = Wqa; C = g_qa; break;
        case 1: W = Wka; C = g_ka; break;
        case 2: W = Wva;
#if HAS_TCGEN05
            C = g_vaT; vt = 1;
#else
            C = g_va;
#endif
            break;
        case 3: W = Wqb; C = g_qb; break;
        case 4: W = Wkb; C = g_kb; break;
        default: W = Wvb;
#if HAS_TCGEN05
            C = g_vbT; vt = 1;
#else
            C = g_vb;
#endif
            break;
    }
    gemm_impl(A, W, C, vt);
}

__global__ __launch_bounds__(256) void oproj_gemm(
    const float* __restrict__ Woa, const float* __restrict__ Wob)
{
    const int z = blockIdx.z;
    const float* A = z ? g_ob : g_oa;
    const float* W = z ? Wob  : Woa;
    float*       C = z ? g_pb : g_pa;
    gemm_impl(A, W, C, 0);
}

// ---------------------------------------------------------------------------
// tcgen05 flash cross-attention, pipelined (R12-validated, 128-key tiles).
// grid (16 q-tiles, 32 bh, 2 branches), 256 threads.
// TMEM: S0 cols [0,128), S1 [128,256), O [256,320).
// ---------------------------------------------------------------------------
#define A_MB1  8
#define A_MB2  16
#define A_LS   32
#define A_Q    2048
#define A_K0   (A_Q + 32768)
#define A_V0   (A_Q + 3 * 32768)
#define ATT_SMEM (A_Q + 6 * 32768)   // 198656

#define IDESC_ATT1 ((1u<<4)|(2u<<7)|(2u<<10)|(16u<<17)|(8u<<24))  // N=128, M=128
#define IDESC_ATT2 ((1u<<4)|(2u<<7)|(2u<<10)|(8u<<17)|(8u<<24))   // N=64,  M=128

#if HAS_TCGEN05
// [128 rows x 64 floats] K-major blocked atoms (16 atom-rows x 2 atom-cols)
__device__ __forceinline__ void att_load_qk(uint32_t base, const float* src,
                                            int row0, int col0, int t)
{
#pragma unroll
    for (int i = 0; i < 8; i++) {
        const int chunk = t + i * 256;
        const int r = chunk >> 4;
        const int c = (chunk & 15) * 4;
        const uint32_t off = (uint32_t)(((r >> 3) + (c >> 5) * 16) * 1024
                           + (r & 7) * 128 + (c & 31) * 4);
        cp16(base + SWZ(off), src + (size_t)(row0 + r) * HALFD + col0 + c);
    }
}
// [64 rows x 128 floats] K-major blocked atoms (8 atom-rows x 4 atom-cols)
__device__ __forceinline__ void att_load_vt(uint32_t base, const float* srcT,
                                            int kt, int t)
{
#pragma unroll
    for (int i = 0; i < 8; i++) {
        const int chunk = t + i * 256;
        const int r = chunk >> 5;
        const int c = (chunk & 31) * 4;
        const uint32_t off = (uint32_t)(((r >> 3) + (c >> 5) * 8) * 1024
                           + (r & 7) * 128 + (c & 31) * 4);
        cp16(base + SWZ(off), srcT + (size_t)r * LEN + kt * 128 + c);
    }
}

__device__ __forceinline__ void att_gemm1(uint32_t sm, uint32_t s_t, int kbuf)
{
    const uint64_t ad = mk_desc(sm + A_Q);
    const uint64_t bd = mk_desc(sm + A_K0 + kbuf * 32768);
#pragma unroll
    for (int kc = 0; kc < 8; kc++) {
        const uint32_t u = (kc >> 2) * 1024 + (kc & 3) * 2;
        mma_tf32_ss(s_t, ad + u, bd + u, IDESC_ATT1, kc > 0);
    }
    tc_commit(sm + A_MB1);
}
#endif

__global__ __launch_bounds__(256) void attn_kernel()
{
#if HAS_TCGEN05
    extern __shared__ char smem[];
    const uint32_t sm = smem_u32(smem);
    const int t = threadIdx.x;
    const int w = t >> 5;
    const int lane = t & 31;
    const int branch = blockIdx.z;
    const int bh = blockIdx.y;
    const int b = bh >> 4, h = bh & 15;
    const int tq = blockIdx.x;

    const float* __restrict__ Q  = branch ? g_qb  : g_qa;
    const float* __restrict__ K  = branch ? g_ka  : g_kb;
    const float* __restrict__ VT = branch ? g_vaT : g_vbT;
    float* __restrict__ O        = branch ? g_ob  : g_oa;
    const float* vt_slice = VT + (size_t)bh * HD * LEN;

    if (w == 0) {
        asm volatile("tcgen05.alloc.cta_group::1.sync.aligned.shared::cta.b32 [%0], %1;"
                     :: "r"(sm + 0), "r"(512u) : "memory");
    }
    if (t == 0) { mbar_init(sm + A_MB1, 1); mbar_init(sm + A_MB2, 1); }
    __syncthreads();
    uint32_t tmem;
    asm volatile("ld.shared.b32 %0, [%1];" : "=r"(tmem) : "r"(sm + 0));
    const uint32_t O_t = tmem + 256;

    const int qrow0 = b * LEN + tq * 128;
    const int krow0 = b * LEN;
    const uint32_t warp_off = (uint32_t)(w & 3) << 21;

    att_load_qk(sm + A_Q,  Q, qrow0, h * HD, t);
    att_load_qk(sm + A_K0, K, krow0, h * HD, t);
    att_load_vt(sm + A_V0, vt_slice, 0, t);
    cp_commit();
    att_load_qk(sm + A_K0 + 32768, K, krow0 + 128, h * HD, t);
    att_load_vt(sm + A_V0 + 32768, vt_slice, 1, t);
    cp_commit();

    cp_wait1();
    __syncthreads();
    if (w == 0) {
        asm volatile("fence.proxy.async.shared::cta;" ::: "memory");
        if (elect1()) att_gemm1(sm, tmem + 0, 0);      // GEMM1(0) -> S0
    }

    // p = exp(s/sqrt(128)) = exp2(s * log2e/sqrt(128))
    const float c_exp2 = 0.12751743f;   // 1.4426950408889634 / sqrt(128)
    float lsum = 0.f;
    const int cb = (w >> 2) * 64;   // this warp's score-column half

    for (int kt = 0; kt < 16; kt++) {
        const uint32_t S_t = tmem + (kt & 1) * 128;

        mbar_wait(sm + A_MB1, kt & 1);
        asm volatile("tcgen05.fence::after_thread_sync;" ::: "memory");

        if (kt + 1 < 16) {
            cp_wait0();
            if (kt >= 1) mbar_wait(sm + A_MB2, (kt - 1) & 1);
            __syncthreads();
            if (w == 0) {
                asm volatile("fence.proxy.async.shared::cta;" ::: "memory");
                if (elect1())
                    att_gemm1(sm, tmem + ((kt + 1) & 1) * 128, (kt + 1) & 1);
            }
            if (kt + 2 < 16) {
                att_load_qk(sm + A_K0 + (kt & 1) * 32768, K,
                            krow0 + (kt + 2) * 128, h * HD, t);
                att_load_vt(sm + A_V0 + ((kt + 2) % 3) * 32768, vt_slice, kt + 2, t);
                cp_commit();
            }
        }

        {
            uint32_t r0[32], r1[32];
            LDTM_X32(r0, S_t + cb + warp_off);
            LDTM_X32(r1, S_t + cb + 32 + warp_off);
            asm volatile("tcgen05.wait::ld.sync.aligned;" ::: "memory");
            float part = 0.f;
#pragma unroll
            for (int j = 0; j < 32; j++) {
                float p = exp2f(__uint_as_float(r0[j]) * c_exp2);
                part += p;
                r0[j] = __float_as_uint(p);
            }
#pragma unroll
            for (int j = 0; j < 32; j++) {
                float p = exp2f(__uint_as_float(r1[j]) * c_exp2);
                part += p;
                r1[j] = __float_as_uint(p);
            }
            lsum += part;
            STTM_X32(S_t + cb + warp_off, r0);
            STTM_X32(S_t + cb + 32 + warp_off, r1);
            asm volatile("tcgen05.wait::st.sync.aligned;" ::: "memory");
            asm volatile("tcgen05.fence::before_thread_sync;" ::: "memory");
        }
        __syncthreads();

        if (w == 0) {
            if (elect1()) {
                asm volatile("tcgen05.fence::after_thread_sync;" ::: "memory");
                const uint64_t bd = mk_desc(sm + A_V0 + (kt % 3) * 32768);
#pragma unroll
                for (int kc = 0; kc < 16; kc++) {
                    const uint64_t u = (kc >> 2) * 512 + (kc & 3) * 2;
                    mma_tf32_ts(O_t, S_t + kc * 8, bd + u, IDESC_ATT2,
                                (kt > 0) || (kc > 0));
                }
                tc_commit(sm + A_MB2);
            }
        }
    }

    float* ls = (float*)(smem + A_LS);
    const int r = (w & 3) * 32 + lane;
    ls[(w >> 2) * 128 + r] = lsum;
    __syncthreads();
    const float inv_l = 1.f / (ls[r] + ls[128 + r]);

    mbar_wait(sm + A_MB2, 1);
    asm volatile("tcgen05.fence::after_thread_sync;" ::: "memory");

    {
        const int c0 = (w >> 2) * 32;
        uint32_t rr[32];
        LDTM_X32(rr, O_t + c0 + warp_off);
        asm volatile("tcgen05.wait::ld.sync.aligned;" ::: "memory");
        float* op = O + (size_t)(qrow0 + r) * HALFD + h * HD + c0;
#pragma unroll
        for (int j = 0; j < 8; j++) {
            float4 v;
            v.x = __uint_as_float(rr[4*j])   * inv_l;
            v.y = __uint_as_float(rr[4*j+1]) * inv_l;
            v.z = __uint_as_float(rr[4*j+2]) * inv_l;
            v.w = __uint_as_float(rr[4*j+3]) * inv_l;
            *(float4*)(op + 4 * j) = v;
        }
    }

    __syncthreads();
    if (t == 0) {
        asm volatile("mbarrier.inval.shared.b64 [%0];" :: "r"(sm + A_MB1) : "memory");
        asm volatile("mbarrier.inval.shared.b64 [%0];" :: "r"(sm + A_MB2) : "memory");
    }
    __syncthreads();
    if (w == 0) {
        asm volatile("tcgen05.relinquish_alloc_permit.cta_group::1.sync.aligned;");
        asm volatile("tcgen05.dealloc.cta_group::1.sync.aligned.b32 %0, %1;"
                     :: "r"(tmem), "r"(512u));
    }
#else
    // ---------------- SIMT f32x2 fallback (reads untransposed V) ----------
    const int branch = blockIdx.z;
    const float* __restrict__ Q = branch ? g_qb : g_qa;
    const float* __restrict__ K = branch ? g_ka : g_kb;
    const float* __restrict__ V = branch ? g_va : g_vb;
    float* __restrict__ O       = branch ? g_ob : g_oa;

    const int bh = blockIdx.y;
    const int b  = bh >> 4;
    const int h  = bh & 15;
    const size_t base = (size_t)b * LEN * HALFD + (size_t)h * HD;

    const int t    = threadIdx.x;
    const int qi   = t >> 1;
    const int half = t & 1;
    const int l    = blockIdx.x * 128 + qi;

    __shared__ __align__(16) float Ks[64][68];
    __shared__ __align__(16) float Vs[64][68];

    const float* qp = Q + base + (size_t)l * HALFD + 4 * half;
    uint64_t q2[16];
    {
        const uint64_t* qd = (const uint64_t*)qp;
#pragma unroll
        for (int j = 0; j < 8; j++) {
            q2[2*j]   = qd[4*j];
            q2[2*j+1] = qd[4*j + 1];
        }
    }

    uint64_t acc2[16];
#pragma unroll
    for (int j = 0; j < 16; j++) acc2[j] = 0ull;
    float mval = -1e30f, lsum = 0.f;
    const float inv_scale = 0.08838834764831845f;

    const int lr = t >> 2;
    const int lc = (t & 3) * 16;

    for (int kt = 0; kt < LEN; kt += 64) {
        __syncthreads();
        {
            const float* kp = K + base + (size_t)(kt + lr) * HALFD + lc;
            const float* vp = V + base + (size_t)(kt + lr) * HALFD + lc;
#pragma unroll
            for (int j = 0; j < 4; j++) {
                *(float4*)&Ks[lr][lc + 4 * j] = *(const float4*)(kp + 4 * j);
                *(float4*)&Vs[lr][lc + 4 * j] = *(const float4*)(vp + 4 * j);
            }
        }
        __syncthreads();

#pragma unroll 2
        for (int k = 0; k < 64; k++) {
            const uint64_t* krow = (const uint64_t*)(&Ks[k][4 * half]);
            uint64_t s2 = 0ull;
#pragma unroll
            for (int j = 0; j < 8; j++) {
                s2 = fma2(q2[2*j],   krow[4*j],     s2);
                s2 = fma2(q2[2*j+1], krow[4*j + 1], s2);
            }
            float slo, shi;
            upk2(s2, slo, shi);
            float s = slo + shi;
            s += __shfl_xor_sync(0xffffffffu, s, 1);
            s *= inv_scale;

            float p;
            if (s > mval) {
                const float cfac = __expf(mval - s);
                mval = s;
                lsum *= cfac;
                const uint64_t c2 = pk2(cfac, cfac);
#pragma unroll
                for (int j = 0; j < 16; j++) acc2[j] = mul2(acc2[j], c2);
                p = 1.f;
            } else {
                p = __expf(s - mval);
            }
            lsum += p;

            const uint64_t p2 = pk2(p, p);
            const uint64_t* vrow = (const uint64_t*)(&Vs[k][4 * half]);
#pragma unroll
            for (int j = 0; j < 8; j++) {
                acc2[2*j]   = fma2(p2, vrow[4*j],     acc2[2*j]);
                acc2[2*j+1] = fma2(p2, vrow[4*j + 1], acc2[2*j+1]);
            }
        }
    }

    const float inv_l = 1.f / lsum;
    const uint64_t inv2 = pk2(inv_l, inv_l);
    uint64_t* od = (uint64_t*)(O + base + (size_t)l * HALFD + 4 * half);
#pragma unroll
    for (int j = 0; j < 8; j++) {
        od[4*j]     = mul2(acc2[2*j],   inv2);
        od[4*j + 1] = mul2(acc2[2*j+1], inv2);
    }
#endif
}

// ---------------------------------------------------------------------------
// Residual + LayerNorm.
// ---------------------------------------------------------------------------
__global__ __launch_bounds__(256) void ln_kernel(
    const float* __restrict__ xa, const float* __restrict__ xb,
    const float* __restrict__ ga, const float* __restrict__ ba,
    const float* __restrict__ gb, const float* __restrict__ bb,
    float* __restrict__ out)
{
    const int row   = blockIdx.x;
    const int which = blockIdx.y;
    const float* x     = which ? xb   : xa;
    const float* p     = which ? g_pb : g_pa;
    const float* gamma = which ? gb   : ga;
    const float* beta  = which ? bb   : ba;
    float* o = out + (size_t)which * ELEMS + (size_t)row * HALFD;

    const int t = threadIdx.x;
    float4 xv = ((const float4*)(x + (size_t)row * HALFD))[t];
    float4 pv = ((const float4*)(p + (size_t)row * HALFD))[t];
    float4 sv = make_float4(xv.x + pv.x, xv.y + pv.y, xv.z + pv.z, xv.w + pv.w);

    float s  = sv.x + sv.y + sv.z + sv.w;
    float sq = sv.x * sv.x + sv.y * sv.y + sv.z * sv.z + sv.w * sv.w;
#pragma unroll
    for (int off = 16; off > 0; off >>= 1) {
        s  += __shfl_xor_sync(0xffffffffu, s,  off);
        sq += __shfl_xor_sync(0xffffffffu, sq, off);
    }
    __shared__ float ss[8], ssq[8];
    if ((t & 31) == 0) { ss[t >> 5] = s; ssq[t >> 5] = sq; }
    __syncthreads();
    float tot = 0.f, totq = 0.f;
#pragma unroll
    for (int i = 0; i < 8; i++) { tot += ss[i]; totq += ssq[i]; }

    const float mean = tot * (1.f / HALFD);
    const float var  = totq * (1.f / HALFD) - mean * mean;
    const float rstd = rsqrtf(var + 1e-5f);

    float4 g4 = ((const float4*)gamma)[t];
    float4 b4 = ((const float4*)beta)[t];
    float4 rr;
    rr.x = (sv.x - mean) * rstd * g4.x + b4.x;
    rr.y = (sv.y - mean) * rstd * g4.y + b4.y;
    rr.z = (sv.z - mean) * rstd * g4.z + b4.z;
    rr.w = (sv.w - mean) * rstd * g4.w + b4.w;
    ((float4*)o)[t] = rr;
}

// ---------------------------------------------------------------------------
extern "C" void kernel_launch(void* const* d_in, const int* in_sizes, int n_in,
                              void* d_out, int out_size)
{
    const float* x_a  = (const float*)d_in[0];
    const float* x_b  = (const float*)d_in[1];
    const float* Wq_a = (const float*)d_in[2];
    const float* Wq_b = (const float*)d_in[3];
    const float* Wk_a = (const float*)d_in[4];
    const float* Wk_b = (const float*)d_in[5];
    const float* Wv_a = (const float*)d_in[6];
    const float* Wv_b = (const float*)d_in[7];
    const float* Wo_a = (const float*)d_in[8];
    const float* Wo_b = (const float*)d_in[9];
    const float* ga   = (const float*)d_in[10];
    const float* ba   = (const float*)d_in[11];
    const float* gb   = (const float*)d_in[12];
    const float* bb   = (const float*)d_in[13];
    float* out = (float*)d_out;

    cudaFuncSetAttribute(qkv_gemm, cudaFuncAttributeMaxDynamicSharedMemorySize,
                         SMEM_GEMM_TOTAL);
    cudaFuncSetAttribute(oproj_gemm, cudaFuncAttributeMaxDynamicSharedMemorySize,
                         SMEM_GEMM_TOTAL);
    cudaFuncSetAttribute(attn_kernel, cudaFuncAttributeMaxDynamicSharedMemorySize,
                         ATT_SMEM);

    dim3 gq(HALFD / GTN, MROWS / GTM, 6);   // (4, 16, 6)
    qkv_gemm<<<gq, 256, SMEM_GEMM_TOTAL>>>(x_a, x_b, Wq_a, Wk_a, Wv_a,
                                           Wq_b, Wk_b, Wv_b);

    dim3 gat(LEN / 128, BN * NH, 2);
    attn_kernel<<<gat, 256, ATT_SMEM>>>();

    dim3 go(HALFD / GTN, MROWS / GTM, 2);   // (4, 16, 2)
    oproj_gemm<<<go, 256, SMEM_GEMM_TOTAL>>>(Wo_a, Wo_b);

    dim3 gl(MROWS, 2);
    ln_kernel<<<gl, 256>>>(x_a, x_b, ga, ba, gb, bb, out);
}

// round 14
// speedup vs baseline: 2.1219x; 1.0420x over previous
#include <cuda_runtime.h>
#include <cstdint>
#include <math.h>

// Problem constants
#define BN    2
#define LEN   2048
#define HALFD 1024
#define NH    16
#define HD    64
#define MROWS (BN * LEN)        // 4096
#define ELEMS (MROWS * HALFD)   // 4194304 per tensor

// Scratch (device globals: no allocation allowed)
__device__ float g_qa[ELEMS];
__device__ float g_ka[ELEMS];
__device__ float g_va[ELEMS];
__device__ float g_qb[ELEMS];
__device__ float g_kb[ELEMS];
__device__ float g_vb[ELEMS];
__device__ float g_oa[ELEMS];
__device__ float g_ob[ELEMS];
__device__ float g_pa[ELEMS];
__device__ float g_pb[ELEMS];
__device__ float g_vaT[ELEMS];   // [bh][64][2048] transposed V, branch a
__device__ float g_vbT[ELEMS];   // [bh][64][2048] transposed V, branch b

#if defined(__CUDA_ARCH__) && (defined(__CUDA_ARCH_FEAT_SM103_ALL) || \
    defined(__CUDA_ARCH_FEAT_SM100_ALL) || defined(__CUDA_ARCH_FEAT_SM101_ALL))
#define HAS_TCGEN05 1
#else
#define HAS_TCGEN05 0
#endif

// ---------------------------------------------------------------------------
// packed f32x2 helpers (legal in plain pass)
// ---------------------------------------------------------------------------
__device__ __forceinline__ uint64_t pk2(float lo, float hi) {
    uint64_t r;
    asm("mov.b64 %0, {%1, %2};" : "=l"(r) : "f"(lo), "f"(hi));
    return r;
}
__device__ __forceinline__ void upk2(uint64_t v, float& lo, float& hi) {
    asm("mov.b64 {%0, %1}, %2;" : "=f"(lo), "=f"(hi) : "l"(v));
}
__device__ __forceinline__ uint64_t fma2(uint64_t a, uint64_t b, uint64_t c) {
    uint64_t d;
    asm("fma.rn.f32x2 %0, %1, %2, %3;" : "=l"(d) : "l"(a), "l"(b), "l"(c));
    return d;
}
__device__ __forceinline__ uint64_t mul2(uint64_t a, uint64_t b) {
    uint64_t d;
    asm("mul.rn.f32x2 %0, %1, %2;" : "=l"(d) : "l"(a), "l"(b));
    return d;
}

// ---------------------------------------------------------------------------
// common asm helpers
// ---------------------------------------------------------------------------
#define SWZ(off) ((off) ^ (((off) >> 3) & 0x70))

__device__ __forceinline__ uint32_t smem_u32(const void* p) {
    uint32_t a;
    asm("{ .reg .u64 t; cvta.to.shared.u64 t, %1; cvt.u32.u64 %0, t; }"
        : "=r"(a) : "l"(p));
    return a;
}
__device__ __forceinline__ void cp16(uint32_t dst, const void* src) {
    asm volatile("cp.async.cg.shared.global [%0], [%1], 16;" :: "r"(dst), "l"(src));
}
__device__ __forceinline__ void cp_commit() {
    asm volatile("cp.async.commit_group;" ::: "memory");
}
__device__ __forceinline__ void cp_wait1() {
    asm volatile("cp.async.wait_group 1;" ::: "memory");
}
__device__ __forceinline__ void cp_wait0() {
    asm volatile("cp.async.wait_group 0;" ::: "memory");
}

#if HAS_TCGEN05
__device__ __forceinline__ uint32_t elect1() {
    uint32_t p;
    asm volatile("{ .reg .pred p; elect.sync _|p, 0xFFFFFFFF; selp.b32 %0,1,0,p; }"
                 : "=r"(p));
    return p;
}
__device__ __forceinline__ void mbar_init(uint32_t a, uint32_t cnt) {
    asm volatile("mbarrier.init.shared.b64 [%0], %1;" :: "r"(a), "r"(cnt) : "memory");
}
__device__ __forceinline__ void mbar_wait(uint32_t a, uint32_t par) {
    asm volatile(
        "{\n\t.reg .pred P;\n"
        "W_%=:\n\t"
        "mbarrier.try_wait.parity.acquire.cta.shared::cta.b64 P, [%0], %1, 0x989680;\n\t"
        "@!P bra W_%=;\n\t}"
        :: "r"(a), "r"(par) : "memory");
}
__device__ __forceinline__ void tc_commit(uint32_t mbar) {
    asm volatile(
        "tcgen05.commit.cta_group::1.mbarrier::arrive::one.shared::cluster.b64 [%0];"
        :: "r"(mbar) : "memory");
}
__device__ __forceinline__ uint64_t mk_desc(uint32_t addr) {
    const uint64_t base = (uint64_t(2) << 61) | (uint64_t(1) << 46)
                        | (uint64_t(64) << 32) | (uint64_t(1) << 16);
    return base | ((uint64_t)(addr >> 4) & 0x3FFF);
}
__device__ __forceinline__ void mma_tf32_ss(uint32_t d, uint64_t ad, uint64_t bd,
                                            uint32_t idesc, uint32_t en) {
    asm volatile(
        "{\n\t.reg .pred p;\n\t"
        "setp.ne.u32 p, %4, 0;\n\t"
        "tcgen05.mma.cta_group::1.kind::tf32 [%0], %1, %2, %3, {%5,%5,%5,%5}, p;\n\t}"
        :: "r"(d), "l"(ad), "l"(bd), "r"(idesc), "r"(en), "r"(0u)
        : "memory");
}
__device__ __forceinline__ void mma_tf32_ts(uint32_t d, uint32_t a, uint64_t bd,
                                            uint32_t idesc, uint32_t en) {
    asm volatile(
        "{\n\t.reg .pred p;\n\t"
        "setp.ne.u32 p, %4, 0;\n\t"
        "tcgen05.mma.cta_group::1.kind::tf32 [%0], [%1], %2, %3, {%5,%5,%5,%5}, p;\n\t}"
        :: "r"(d), "r"(a), "l"(bd), "r"(idesc), "r"(en), "r"(0u)
        : "memory");
}

#define LDTM_X32(r, addr) \
    asm volatile( \
        "tcgen05.ld.sync.aligned.32x32b.x32.b32 " \
        "{%0,%1,%2,%3,%4,%5,%6,%7,%8,%9,%10,%11,%12,%13,%14,%15," \
        "%16,%17,%18,%19,%20,%21,%22,%23,%24,%25,%26,%27,%28,%29,%30,%31}, [%32];" \
        : "=r"((r)[0]), "=r"((r)[1]), "=r"((r)[2]), "=r"((r)[3]), \
          "=r"((r)[4]), "=r"((r)[5]), "=r"((r)[6]), "=r"((r)[7]), \
          "=r"((r)[8]), "=r"((r)[9]), "=r"((r)[10]), "=r"((r)[11]), \
          "=r"((r)[12]), "=r"((r)[13]), "=r"((r)[14]), "=r"((r)[15]), \
          "=r"((r)[16]), "=r"((r)[17]), "=r"((r)[18]), "=r"((r)[19]), \
          "=r"((r)[20]), "=r"((r)[21]), "=r"((r)[22]), "=r"((r)[23]), \
          "=r"((r)[24]), "=r"((r)[25]), "=r"((r)[26]), "=r"((r)[27]), \
          "=r"((r)[28]), "=r"((r)[29]), "=r"((r)[30]), "=r"((r)[31]) \
        : "r"(addr))

#define STTM_X32(addr, r) \
    asm volatile( \
        "tcgen05.st.sync.aligned.32x32b.x32.b32 [%0], " \
        "{%1,%2,%3,%4,%5,%6,%7,%8,%9,%10,%11,%12,%13,%14,%15,%16," \
        "%17,%18,%19,%20,%21,%22,%23,%24,%25,%26,%27,%28,%29,%30,%31,%32};" \
        :: "r"(addr), \
           "r"((r)[0]), "r"((r)[1]), "r"((r)[2]), "r"((r)[3]), \
           "r"((r)[4]), "r"((r)[5]), "r"((r)[6]), "r"((r)[7]), \
           "r"((r)[8]), "r"((r)[9]), "r"((r)[10]), "r"((r)[11]), \
           "r"((r)[12]), "r"((r)[13]), "r"((r)[14]), "r"((r)[15]), \
           "r"((r)[16]), "r"((r)[17]), "r"((r)[18]), "r"((r)[19]), \
           "r"((r)[20]), "r"((r)[21]), "r"((r)[22]), "r"((r)[23]), \
           "r"((r)[24]), "r"((r)[25]), "r"((r)[26]), "r"((r)[27]), \
           "r"((r)[28]), "r"((r)[29]), "r"((r)[30]), "r"((r)[31]) \
        : "memory")
#endif  // HAS_TCGEN05

// ---------------------------------------------------------------------------
// Projection GEMM (R13-validated): C[m,n] = sum_k A[m,k]*W[n,k].
// Tile 256x256, K staged 32 floats, 3 buffers, shifted pipeline.
// vt=1 epilogue writes V directly in [bh][d][tok] transposed layout.
// ---------------------------------------------------------------------------
#define GTM 256
#define GTN 256
#define KSTEP 32
#define NSTAGES (HALFD / KSTEP)     // 32
#define G_NBUF 3
#define G_ABYTES  32768             // 256 rows x 128B
#define G_BUFSTRIDE 65536
#define SM_MBAR  8
#define SM_TILES 1024
#define SMEM_GEMM_TOTAL (SM_TILES + G_NBUF * G_BUFSTRIDE)   // 197632

// per-MMA idesc: M=128, N=256, tf32
#define IDESC_G ((1u<<4)|(2u<<7)|(2u<<10)|((GTN/8)<<17)|(8u<<24))

__device__ __forceinline__ void g_load_stage(uint32_t sm_base,
                                             const float* __restrict__ A,
                                             const float* __restrict__ W,
                                             int bm, int bn, int s, int buf, int t)
{
    const int k0  = s * KSTEP;
    const int rb  = t >> 3;        // 0..31
    const int c16 = (t & 7);       // 16B chunk within 128B row
    const uint32_t abase = sm_base + SM_TILES + buf * G_BUFSTRIDE;
    const uint32_t bbase = abase + G_ABYTES;
#pragma unroll
    for (int i = 0; i < 8; i++) {
        const int row = i * 32 + rb;
        const uint32_t off = row * 128 + c16 * 16;
        cp16(abase + SWZ(off), A + (size_t)(bm + row) * HALFD + k0 + c16 * 4);
    }
#pragma unroll
    for (int i = 0; i < 8; i++) {
        const int row = i * 32 + rb;
        const uint32_t off = row * 128 + c16 * 16;
        cp16(bbase + SWZ(off), W + (size_t)(bn + row) * HALFD + k0 + c16 * 4);
    }
}

#if !HAS_TCGEN05
// SIMT f32x2 128x128 sub-tile (fallback only)
__device__ void gemm128_fb(const float* __restrict__ A,
                           const float* __restrict__ W,
                           float* __restrict__ C, int bm, int bn)
{
    __shared__ float As[16][128];
    __shared__ float Bs[16][128];
    const int t  = threadIdx.x;
    const int tm = (t >> 4) * 8;
    const int tn = (t & 15) * 8;

    uint64_t acc2[8][4];
#pragma unroll
    for (int i = 0; i < 8; i++)
#pragma unroll
        for (int j = 0; j < 4; j++) acc2[i][j] = 0ull;

    const int lrow = t >> 2;
    const int lkc  = (t & 3) * 4;
    const int swz  = (t & 3) * 8;

    for (int k0 = 0; k0 < 1024; k0 += 16) {
#pragma unroll
        for (int i = 0; i < 2; i++) {
            const int row = lrow + i * 64;
            float4 a = *(const float4*)(A + (size_t)(bm + row) * 1024 + k0 + lkc);
            float4 b = *(const float4*)(W + (size_t)(bn + row) * 1024 + k0 + lkc);
            const int sc = row ^ swz;
            As[lkc + 0][sc] = a.x; As[lkc + 1][sc] = a.y;
            As[lkc + 2][sc] = a.z; As[lkc + 3][sc] = a.w;
            Bs[lkc + 0][sc] = b.x; Bs[lkc + 1][sc] = b.y;
            Bs[lkc + 2][sc] = b.z; Bs[lkc + 3][sc] = b.w;
        }
        __syncthreads();
#pragma unroll
        for (int kk = 0; kk < 16; kk++) {
            const int sa = (kk >> 2) * 8;
            const int ca = tm ^ sa;
            const int cb = tn ^ sa;
            float a8[8];
            *(float4*)&a8[0] = *(const float4*)&As[kk][ca];
            *(float4*)&a8[4] = *(const float4*)&As[kk][ca + 4];
            float4 b0 = *(const float4*)&Bs[kk][cb];
            float4 b1 = *(const float4*)&Bs[kk][cb + 4];
            uint64_t b2[4];
            b2[0] = pk2(b0.x, b0.y); b2[1] = pk2(b0.z, b0.w);
            b2[2] = pk2(b1.x, b1.y); b2[3] = pk2(b1.z, b1.w);
#pragma unroll
            for (int i = 0; i < 8; i++) {
                const uint64_t ai = pk2(a8[i], a8[i]);
#pragma unroll
                for (int j = 0; j < 4; j++)
                    acc2[i][j] = fma2(ai, b2[j], acc2[i][j]);
            }
        }
        __syncthreads();
    }
#pragma unroll
    for (int i = 0; i < 8; i++) {
        float c[8];
#pragma unroll
        for (int j = 0; j < 4; j++) upk2(acc2[i][j], c[2*j], c[2*j+1]);
        float* cp = C + (size_t)(bm + tm + i) * 1024 + bn + tn;
        *(float4*)(cp)     = make_float4(c[0], c[1], c[2], c[3]);
        *(float4*)(cp + 4) = make_float4(c[4], c[5], c[6], c[7]);
    }
}
#endif

__device__ void gemm_impl(const float* __restrict__ A,
                          const float* __restrict__ W,
                          float* __restrict__ C, int vt)
{
#if HAS_TCGEN05
    extern __shared__ char smem[];
    const uint32_t sm_base = smem_u32(smem);
    const int t   = threadIdx.x;
    const int wid = t >> 5;
    const int lid = t & 31;
    const int bm  = blockIdx.y * GTM;
    const int bn  = blockIdx.x * GTN;

    if (wid == 0) {
        asm volatile("tcgen05.alloc.cta_group::1.sync.aligned.shared::cta.b32 [%0], %1;"
                     :: "r"(sm_base + 0), "r"(512u) : "memory");
    }
    if (t == 0) {
        mbar_init(sm_base + SM_MBAR + 0, 1);
        mbar_init(sm_base + SM_MBAR + 8, 1);
        mbar_init(sm_base + SM_MBAR + 16, 1);
    }
    __syncthreads();
    uint32_t tmem;
    asm volatile("ld.shared.b32 %0, [%1];" : "=r"(tmem) : "r"(sm_base + 0));

    g_load_stage(sm_base, A, W, bm, bn, 0, 0, t); cp_commit();
    g_load_stage(sm_base, A, W, bm, bn, 1, 1, t); cp_commit();

    for (int s = 0; s < NSTAGES; s++) {
        const int buf = s % 3;
        if (s == NSTAGES - 1) cp_wait0(); else cp_wait1();
        __syncthreads();

        if (wid == 0) {
            asm volatile("fence.proxy.async.shared::cta;" ::: "memory");
            if (elect1()) {
                const uint32_t ab = sm_base + SM_TILES + buf * G_BUFSTRIDE;
                const uint64_t ad0 = mk_desc(ab);
                const uint64_t ad1 = mk_desc(ab + 16384);
                const uint64_t bd  = mk_desc(ab + G_ABYTES);
#pragma unroll
                for (int c = 0; c < 4; c++) {
                    const uint32_t en = (s > 0) || (c > 0);
                    mma_tf32_ss(tmem,       ad0 + 2 * c, bd + 2 * c, IDESC_G, en);
                    mma_tf32_ss(tmem + 256, ad1 + 2 * c, bd + 2 * c, IDESC_G, en);
                }
                tc_commit(sm_base + SM_MBAR + 8 * buf);
            }
        }

        if (s + 2 < NSTAGES) {
            if (s >= 1)
                mbar_wait(sm_base + SM_MBAR + 8 * ((s - 1) % 3),
                          (uint32_t)(((s - 1) / 3) & 1));
            g_load_stage(sm_base, A, W, bm, bn, s + 2, (s + 2) % 3, t);
            cp_commit();
        }
    }

    mbar_wait(sm_base + SM_MBAR + 8 * ((NSTAGES - 1) % 3),
              (uint32_t)(((NSTAGES - 1) / 3) & 1));
    asm volatile("tcgen05.fence::after_thread_sync;" ::: "memory");

    {
        const int dtile = wid >> 2;
        const int row = bm + dtile * 128 + (wid & 3) * 32 + lid;
        if (!vt) {
#pragma unroll
            for (int cc = 0; cc < 8; cc++) {
                uint32_t r[32];
                LDTM_X32(r, tmem + dtile * 256 + cc * 32);
                asm volatile("tcgen05.wait::ld.sync.aligned;" ::: "memory");
                float* cp = C + (size_t)row * HALFD + bn + cc * 32;
#pragma unroll
                for (int j = 0; j < 8; j++)
                    *(uint4*)(cp + 4 * j) = make_uint4(r[4*j], r[4*j+1], r[4*j+2], r[4*j+3]);
            }
        } else {
            const int tok = row & (LEN - 1);
            const int bidx = row >> 11;
            float* dstb = C + (size_t)bidx * 1024 * LEN + tok;
#pragma unroll
            for (int cc = 0; cc < 8; cc++) {
                uint32_t r[32];
                LDTM_X32(r, tmem + dtile * 256 + cc * 32);
                asm volatile("tcgen05.wait::ld.sync.aligned;" ::: "memory");
                const int f0 = bn + cc * 32;
#pragma unroll
                for (int j = 0; j < 32; j++)
                    dstb[(size_t)(f0 + j) * LEN] = __uint_as_float(r[j]);
            }
        }
    }

    __syncthreads();
    if (t == 0) {
        asm volatile("mbarrier.inval.shared.b64 [%0];" :: "r"(sm_base + SM_MBAR + 0) : "memory");
        asm volatile("mbarrier.inval.shared.b64 [%0];" :: "r"(sm_base + SM_MBAR + 8) : "memory");
        asm volatile("mbarrier.inval.shared.b64 [%0];" :: "r"(sm_base + SM_MBAR + 16) : "memory");
    }
    __syncthreads();
    if (wid == 0) {
        asm volatile("tcgen05.relinquish_alloc_permit.cta_group::1.sync.aligned;");
        asm volatile("tcgen05.dealloc.cta_group::1.sync.aligned.b32 %0, %1;"
                     :: "r"(tmem), "r"(512u));
    }
#else
    (void)vt;
    const int bm = blockIdx.y * GTM;
    const int bn = blockIdx.x * GTN;
#pragma unroll
    for (int ii = 0; ii < 2; ii++)
#pragma unroll
        for (int jj = 0; jj < 2; jj++)
            gemm128_fb(A, W, C, bm + ii * 128, bn + jj * 128);
#endif
}

__global__ __launch_bounds__(256) void qkv_gemm(
    const float* __restrict__ xa, const float* __restrict__ xb,
    const float* __restrict__ Wqa, const float* __restrict__ Wka, const float* __restrict__ Wva,
    const float* __restrict__ Wqb, const float* __restrict__ Wkb, const float* __restrict__ Wvb)
{
    const int z = blockIdx.z;
    const float* A = (z < 3) ? xa : xb;
    const float* W;
    float* C;
    int vt = 0;
    switch (z) {
        case 0: W = Wqa; C = g_qa; break;
        case 1: W = Wka; C = g_ka; break;
        case 2: W = Wva;
#if HAS_TCGEN05
            C = g_vaT; vt = 1;
#else
            C = g_va;
#endif
            break;
        case 3: W = Wqb; C = g_qb; break;
        case 4: W = Wkb; C = g_kb; break;
        default: W = Wvb;
#if HAS_TCGEN05
            C = g_vbT; vt = 1;
#else
            C = g_vb;
#endif
            break;
    }
    gemm_impl(A, W, C, vt);
}

__global__ __launch_bounds__(256) void oproj_gemm(
    const float* __restrict__ Woa, const float* __restrict__ Wob)
{
    const int z = blockIdx.z;
    const float* A = z ? g_ob : g_oa;
    const float* W = z ? Wob  : Woa;
    float*       C = z ? g_pb : g_pa;
    gemm_impl(A, W, C, 0);
}

// ---------------------------------------------------------------------------
// tcgen05 flash cross-attention, persistent CTAs with cross-tile prefetch.
// grid 148 persistent CTAs; 1024 tiles strided. Per tile: 16 x 128-key steps.
// TMEM: S0 [0,128), S1 [128,256), O [256,320). MB1/MB2 advance 16 phases per
// tile -> all parity expressions tile-invariant. V ring base vb advances
// (+16 mod 3 = +1) per tile. Next tile's K0/V0 prefetched at kt=14 (after the
// MB2(13) wait frees them), Q/K1/V1 at kt=15 (after MB1(15) + MB2(14) waits).
// ---------------------------------------------------------------------------
#define A_MB1  8
#define A_MB2  16
#define A_LS   32
#define A_Q    2048
#define A_K0   (A_Q + 32768)
#define A_V0   (A_Q + 3 * 32768)
#define ATT_SMEM (A_Q + 6 * 32768)   // 198656
#define ATT_TILES 1024
#define ATT_GRID  148

#define IDESC_ATT1 ((1u<<4)|(2u<<7)|(2u<<10)|(16u<<17)|(8u<<24))  // N=128, M=128
#define IDESC_ATT2 ((1u<<4)|(2u<<7)|(2u<<10)|(8u<<17)|(8u<<24))   // N=64,  M=128

#if HAS_TCGEN05
// [128 rows x 64 floats] K-major blocked atoms (16 atom-rows x 2 atom-cols)
__device__ __forceinline__ void att_load_qk(uint32_t base, const float* src,
                                            int row0, int col0, int t)
{
#pragma unroll
    for (int i = 0; i < 8; i++) {
        const int chunk = t + i * 256;
        const int r = chunk >> 4;
        const int c = (chunk & 15) * 4;
        const uint32_t off = (uint32_t)(((r >> 3) + (c >> 5) * 16) * 1024
                           + (r & 7) * 128 + (c & 31) * 4);
        cp16(base + SWZ(off), src + (size_t)(row0 + r) * HALFD + col0 + c);
    }
}
// [64 rows x 128 floats] K-major blocked atoms (8 atom-rows x 4 atom-cols)
__device__ __forceinline__ void att_load_vt(uint32_t base, const float* srcT,
                                            int kt, int t)
{
#pragma unroll
    for (int i = 0; i < 8; i++) {
        const int chunk = t + i * 256;
        const int r = chunk >> 5;
        const int c = (chunk & 31) * 4;
        const uint32_t off = (uint32_t)(((r >> 3) + (c >> 5) * 8) * 1024
                           + (r & 7) * 128 + (c & 31) * 4);
        cp16(base + SWZ(off), srcT + (size_t)r * LEN + kt * 128 + c);
    }
}

__device__ __forceinline__ void att_gemm1(uint32_t sm, uint32_t s_t, int kbuf)
{
    const uint64_t ad = mk_desc(sm + A_Q);
    const uint64_t bd = mk_desc(sm + A_K0 + kbuf * 32768);
#pragma unroll
    for (int kc = 0; kc < 8; kc++) {
        const uint32_t u = (kc >> 2) * 1024 + (kc & 3) * 2;
        mma_tf32_ss(s_t, ad + u, bd + u, IDESC_ATT1, kc > 0);
    }
    tc_commit(sm + A_MB1);
}
#endif

__global__ __launch_bounds__(256) void attn_kernel()
{
#if HAS_TCGEN05
    extern __shared__ char smem[];
    const uint32_t sm = smem_u32(smem);
    const int t = threadIdx.x;
    const int w = t >> 5;
    const int lane = t & 31;
    const int bid = blockIdx.x;

    if (w == 0) {
        asm volatile("tcgen05.alloc.cta_group::1.sync.aligned.shared::cta.b32 [%0], %1;"
                     :: "r"(sm + 0), "r"(512u) : "memory");
    }
    if (t == 0) { mbar_init(sm + A_MB1, 1); mbar_init(sm + A_MB2, 1); }
    __syncthreads();
    uint32_t tmem;
    asm volatile("ld.shared.b32 %0, [%1];" : "=r"(tmem) : "r"(sm + 0));
    const uint32_t O_t = tmem + 256;
    const uint32_t warp_off = (uint32_t)(w & 3) << 21;
    const float c_exp2 = 0.12751743f;   // log2e / sqrt(128)
    const int cb = (w >> 2) * 64;

    int vb = 0;   // V-ring base, advances +1 per tile

    for (int tile = bid; tile < ATT_TILES; tile += ATT_GRID) {
        const int branch = tile >> 9;
        const int bh = (tile >> 4) & 31;
        const int tq = tile & 15;
        const int b = bh >> 4, h = bh & 15;
        const float* __restrict__ Q  = branch ? g_qb  : g_qa;
        const float* __restrict__ K  = branch ? g_ka  : g_kb;
        const float* vt_slice = (branch ? g_vaT : g_vbT) + (size_t)bh * HD * LEN;
        float* __restrict__ O        = branch ? g_ob  : g_oa;
        const int qrow0 = b * LEN + tq * 128;
        const int krow0 = b * LEN;

        const int ntile = tile + ATT_GRID;
        const int has_next = ntile < ATT_TILES;

        if (tile == bid) {
            // first tile of this CTA: full prologue loads
            att_load_qk(sm + A_Q,  Q, qrow0, h * HD, t);
            att_load_qk(sm + A_K0, K, krow0, h * HD, t);
            att_load_vt(sm + A_V0 + vb * 32768, vt_slice, 0, t);
            cp_commit();
            att_load_qk(sm + A_K0 + 32768, K, krow0 + 128, h * HD, t);
            att_load_vt(sm + A_V0 + ((vb + 1) % 3) * 32768, vt_slice, 1, t);
            cp_commit();
        }

        cp_wait0();
        __syncthreads();
        if (w == 0) {
            asm volatile("fence.proxy.async.shared::cta;" ::: "memory");
            if (elect1()) att_gemm1(sm, tmem + 0, 0);   // GEMM1(0) -> S0
        }

        float lsum = 0.f;

        for (int kt = 0; kt < 16; kt++) {
            const uint32_t S_t = tmem + (kt & 1) * 128;

            mbar_wait(sm + A_MB1, kt & 1);
            asm volatile("tcgen05.fence::after_thread_sync;" ::: "memory");

            if (kt < 15) {
                cp_wait0();
                if (kt >= 1) mbar_wait(sm + A_MB2, (kt - 1) & 1);
                __syncthreads();
                if (w == 0) {
                    asm volatile("fence.proxy.async.shared::cta;" ::: "memory");
                    if (elect1())
                        att_gemm1(sm, tmem + ((kt + 1) & 1) * 128, (kt + 1) & 1);
                }
                if (kt + 2 < 16) {
                    att_load_qk(sm + A_K0 + (kt & 1) * 32768, K,
                                krow0 + (kt + 2) * 128, h * HD, t);
                    att_load_vt(sm + A_V0 + ((vb + kt + 2) % 3) * 32768,
                                vt_slice, kt + 2, t);
                    cp_commit();
                } else if (has_next) {   // kt == 14: next tile's K0, V0
                    const int nbr = ntile >> 9;
                    const int nbh = (ntile >> 4) & 31;
                    const int nb = nbh >> 4, nh = nbh & 15;
                    const float* nK = nbr ? g_ka : g_kb;
                    const float* nVT = (nbr ? g_vaT : g_vbT) + (size_t)nbh * HD * LEN;
                    att_load_qk(sm + A_K0, nK, nb * LEN, nh * HD, t);   // buf0
                    att_load_vt(sm + A_V0 + ((vb + 1) % 3) * 32768, nVT, 0, t);
                    cp_commit();
                }
            } else if (has_next) {       // kt == 15: next tile's Q, K1, V1
                mbar_wait(sm + A_MB2, 0);   // GEMM2(14) done -> buffers free
                const int nbr = ntile >> 9;
                const int nbh = (ntile >> 4) & 31;
                const int ntq = ntile & 15;
                const int nb = nbh >> 4, nh = nbh & 15;
                const float* nQ = nbr ? g_qb : g_qa;
                const float* nK = nbr ? g_ka : g_kb;
                const float* nVT = (nbr ? g_vaT : g_vbT) + (size_t)nbh * HD * LEN;
                att_load_qk(sm + A_Q, nQ, nb * LEN + ntq * 128, nh * HD, t);
                att_load_qk(sm + A_K0 + 32768, nK, nb * LEN + 128, nh * HD, t);
                att_load_vt(sm + A_V0 + ((vb + 2) % 3) * 32768, nVT, 1, t);
                cp_commit();
            }

            // softmax(kt): p = exp2(s * c_exp2), in place S -> P
            {
                uint32_t r0[32], r1[32];
                LDTM_X32(r0, S_t + cb + warp_off);
                LDTM_X32(r1, S_t + cb + 32 + warp_off);
                asm volatile("tcgen05.wait::ld.sync.aligned;" ::: "memory");
                float part = 0.f;
#pragma unroll
                for (int j = 0; j < 32; j++) {
                    float p = exp2f(__uint_as_float(r0[j]) * c_exp2);
                    part += p;
                    r0[j] = __float_as_uint(p);
                }
#pragma unroll
                for (int j = 0; j < 32; j++) {
                    float p = exp2f(__uint_as_float(r1[j]) * c_exp2);
                    part += p;
                    r1[j] = __float_as_uint(p);
                }
                lsum += part;
                STTM_X32(S_t + cb + warp_off, r0);
                STTM_X32(S_t + cb + 32 + warp_off, r1);
                asm volatile("tcgen05.wait::st.sync.aligned;" ::: "memory");
                asm volatile("tcgen05.fence::before_thread_sync;" ::: "memory");
            }
            __syncthreads();

            if (w == 0) {
                if (elect1()) {
                    asm volatile("tcgen05.fence::after_thread_sync;" ::: "memory");
                    const uint64_t bd = mk_desc(sm + A_V0 + ((vb + kt) % 3) * 32768);
#pragma unroll
                    for (int kc = 0; kc < 16; kc++) {
                        const uint64_t u = (kc >> 2) * 512 + (kc & 3) * 2;
                        mma_tf32_ts(O_t, S_t + kc * 8, bd + u, IDESC_ATT2,
                                    (kt > 0) || (kc > 0));
                    }
                    tc_commit(sm + A_MB2);
                }
            }
        }

        // combine row sums from the two column-half warps
        float* ls = (float*)(smem + A_LS);
        const int r = (w & 3) * 32 + lane;
        ls[(w >> 2) * 128 + r] = lsum;
        __syncthreads();
        const float inv_l = 1.f / (ls[r] + ls[128 + r]);

        mbar_wait(sm + A_MB2, 1);
        asm volatile("tcgen05.fence::after_thread_sync;" ::: "memory");

        {
            const int c0 = (w >> 2) * 32;
            uint32_t rr[32];
            LDTM_X32(rr, O_t + c0 + warp_off);
            asm volatile("tcgen05.wait::ld.sync.aligned;" ::: "memory");
            float* op = O + (size_t)(qrow0 + r) * HALFD + h * HD + c0;
#pragma unroll
            for (int j = 0; j < 8; j++) {
                float4 v;
                v.x = __uint_as_float(rr[4*j])   * inv_l;
                v.y = __uint_as_float(rr[4*j+1]) * inv_l;
                v.z = __uint_as_float(rr[4*j+2]) * inv_l;
                v.w = __uint_as_float(rr[4*j+3]) * inv_l;
                *(float4*)(op + 4 * j) = v;
            }
        }
        __syncthreads();   // all warps done with ls + epilogue before next tile

        vb = (vb + 1) % 3;
    }

    if (t == 0) {
        asm volatile("mbarrier.inval.shared.b64 [%0];" :: "r"(sm + A_MB1) : "memory");
        asm volatile("mbarrier.inval.shared.b64 [%0];" :: "r"(sm + A_MB2) : "memory");
    }
    __syncthreads();
    if (w == 0) {
        asm volatile("tcgen05.relinquish_alloc_permit.cta_group::1.sync.aligned;");
        asm volatile("tcgen05.dealloc.cta_group::1.sync.aligned.b32 %0, %1;"
                     :: "r"(tmem), "r"(512u));
    }
#else
    // ---------------- SIMT f32x2 fallback (reads untransposed V) ----------
    const int bid = blockIdx.x;
    const int t    = threadIdx.x;
    const int qi   = t >> 1;
    const int half = t & 1;

    __shared__ __align__(16) float Ks[64][68];
    __shared__ __align__(16) float Vs[64][68];

    for (int tile = bid; tile < ATT_TILES; tile += ATT_GRID) {
        const int branch = tile >> 9;
        const int bh = (tile >> 4) & 31;
        const int tq = tile & 15;
        const float* __restrict__ Q = branch ? g_qb : g_qa;
        const float* __restrict__ K = branch ? g_ka : g_kb;
        const float* __restrict__ V = branch ? g_va : g_vb;
        float* __restrict__ O       = branch ? g_ob : g_oa;
        const int b  = bh >> 4;
        const int h  = bh & 15;
        const size_t base = (size_t)b * LEN * HALFD + (size_t)h * HD;
        const int l = tq * 128 + qi;

        const float* qp = Q + base + (size_t)l * HALFD + 4 * half;
        uint64_t q2[16];
        {
            const uint64_t* qd = (const uint64_t*)qp;
#pragma unroll
            for (int j = 0; j < 8; j++) {
                q2[2*j]   = qd[4*j];
                q2[2*j+1] = qd[4*j + 1];
            }
        }

        uint64_t acc2[16];
#pragma unroll
        for (int j = 0; j < 16; j++) acc2[j] = 0ull;
        float mval = -1e30f, lsum = 0.f;
        const float inv_scale = 0.08838834764831845f;

        const int lr = t >> 2;
        const int lc = (t & 3) * 16;

        for (int kt = 0; kt < LEN; kt += 64) {
            __syncthreads();
            {
                const float* kp = K + base + (size_t)(kt + lr) * HALFD + lc;
                const float* vp = V + base + (size_t)(kt + lr) * HALFD + lc;
#pragma unroll
                for (int j = 0; j < 4; j++) {
                    *(float4*)&Ks[lr][lc + 4 * j] = *(const float4*)(kp + 4 * j);
                    *(float4*)&Vs[lr][lc + 4 * j] = *(const float4*)(vp + 4 * j);
                }
            }
            __syncthreads();

#pragma unroll 2
            for (int k = 0; k < 64; k++) {
                const uint64_t* krow = (const uint64_t*)(&Ks[k][4 * half]);
                uint64_t s2 = 0ull;
#pragma unroll
                for (int j = 0; j < 8; j++) {
                    s2 = fma2(q2[2*j],   krow[4*j],     s2);
                    s2 = fma2(q2[2*j+1], krow[4*j + 1], s2);
                }
                float slo, shi;
                upk2(s2, slo, shi);
                float s = slo + shi;
                s += __shfl_xor_sync(0xffffffffu, s, 1);
                s *= inv_scale;

                float p;
                if (s > mval) {
                    const float cfac = __expf(mval - s);
                    mval = s;
                    lsum *= cfac;
                    const uint64_t c2 = pk2(cfac, cfac);
#pragma unroll
                    for (int j = 0; j < 16; j++) acc2[j] = mul2(acc2[j], c2);
                    p = 1.f;
                } else {
                    p = __expf(s - mval);
                }
                lsum += p;

                const uint64_t p2 = pk2(p, p);
                const uint64_t* vrow = (const uint64_t*)(&Vs[k][4 * half]);
#pragma unroll
                for (int j = 0; j < 8; j++) {
                    acc2[2*j]   = fma2(p2, vrow[4*j],     acc2[2*j]);
                    acc2[2*j+1] = fma2(p2, vrow[4*j + 1], acc2[2*j+1]);
                }
            }
        }

        const float inv_l = 1.f / lsum;
        const uint64_t inv2 = pk2(inv_l, inv_l);
        uint64_t* od = (uint64_t*)(O + base + (size_t)l * HALFD + 4 * half);
#pragma unroll
        for (int j = 0; j < 8; j++) {
            od[4*j]     = mul2(acc2[2*j],   inv2);
            od[4*j + 1] = mul2(acc2[2*j+1], inv2);
        }
    }
#endif
}

// ---------------------------------------------------------------------------
// Residual + LayerNorm.
// ---------------------------------------------------------------------------
__global__ __launch_bounds__(256) void ln_kernel(
    const float* __restrict__ xa, const float* __restrict__ xb,
    const float* __restrict__ ga, const float* __restrict__ ba,
    const float* __restrict__ gb, const float* __restrict__ bb,
    float* __restrict__ out)
{
    const int row   = blockIdx.x;
    const int which = blockIdx.y;
    const float* x     = which ? xb   : xa;
    const float* p     = which ? g_pb : g_pa;
    const float* gamma = which ? gb   : ga;
    const float* beta  = which ? bb   : ba;
    float* o = out + (size_t)which * ELEMS + (size_t)row * HALFD;

    const int t = threadIdx.x;
    float4 xv = ((const float4*)(x + (size_t)row * HALFD))[t];
    float4 pv = ((const float4*)(p + (size_t)row * HALFD))[t];
    float4 sv = make_float4(xv.x + pv.x, xv.y + pv.y, xv.z + pv.z, xv.w + pv.w);

    float s  = sv.x + sv.y + sv.z + sv.w;
    float sq = sv.x * sv.x + sv.y * sv.y + sv.z * sv.z + sv.w * sv.w;
#pragma unroll
    for (int off = 16; off > 0; off >>= 1) {
        s  += __shfl_xor_sync(0xffffffffu, s,  off);
        sq += __shfl_xor_sync(0xffffffffu, sq, off);
    }
    __shared__ float ss[8], ssq[8];
    if ((t & 31) == 0) { ss[t >> 5] = s; ssq[t >> 5] = sq; }
    __syncthreads();
    float tot = 0.f, totq = 0.f;
#pragma unroll
    for (int i = 0; i < 8; i++) { tot += ss[i]; totq += ssq[i]; }

    const float mean = tot * (1.f / HALFD);
    const float var  = totq * (1.f / HALFD) - mean * mean;
    const float rstd = rsqrtf(var + 1e-5f);

    float4 g4 = ((const float4*)gamma)[t];
    float4 b4 = ((const float4*)beta)[t];
    float4 rr;
    rr.x = (sv.x - mean) * rstd * g4.x + b4.x;
    rr.y = (sv.y - mean) * rstd * g4.y + b4.y;
    rr.z = (sv.z - mean) * rstd * g4.z + b4.z;
    rr.w = (sv.w - mean) * rstd * g4.w + b4.w;
    ((float4*)o)[t] = rr;
}

// ---------------------------------------------------------------------------
extern "C" void kernel_launch(void* const* d_in, const int* in_sizes, int n_in,
                              void* d_out, int out_size)
{
    const float* x_a  = (const float*)d_in[0];
    const float* x_b  = (const float*)d_in[1];
    const float* Wq_a = (const float*)d_in[2];
    const float* Wq_b = (const float*)d_in[3];
    const float* Wk_a = (const float*)d_in[4];
    const float* Wk_b = (const float*)d_in[5];
    const float* Wv_a = (const float*)d_in[6];
    const float* Wv_b = (const float*)d_in[7];
    const float* Wo_a = (const float*)d_in[8];
    const float* Wo_b = (const float*)d_in[9];
    const float* ga   = (const float*)d_in[10];
    const float* ba   = (const float*)d_in[11];
    const float* gb   = (const float*)d_in[12];
    const float* bb   = (const float*)d_in[13];
    float* out = (float*)d_out;

    cudaFuncSetAttribute(qkv_gemm, cudaFuncAttributeMaxDynamicSharedMemorySize,
                         SMEM_GEMM_TOTAL);
    cudaFuncSetAttribute(oproj_gemm, cudaFuncAttributeMaxDynamicSharedMemorySize,
                         SMEM_GEMM_TOTAL);
    cudaFuncSetAttribute(attn_kernel, cudaFuncAttributeMaxDynamicSharedMemorySize,
                         ATT_SMEM);

    dim3 gq(HALFD / GTN, MROWS / GTM, 6);   // (4, 16, 6)
    qkv_gemm<<<gq, 256, SMEM_GEMM_TOTAL>>>(x_a, x_b, Wq_a, Wk_a, Wv_a,
                                           Wq_b, Wk_b, Wv_b);

    attn_kernel<<<ATT_GRID, 256, ATT_SMEM>>>();

    dim3 go(HALFD / GTN, MROWS / GTM, 2);   // (4, 16, 2)
    oproj_gemm<<<go, 256, SMEM_GEMM_TOTAL>>>(Wo_a, Wo_b);

    dim3 gl(MROWS, 2);
    ln_kernel<<<gl, 256>>>(x_a, x_b, ga, ba, gb, bb, out);
}